// round 15
// baseline (speedup 1.0000x reference)
#include <cuda_runtime.h>
#include <cuda_bf16.h>
#include <math.h>
#include <stdint.h>

#define D 128
#define MAX_N   400000
#define MAX_E1  1000000
#define MAX_E2  500000
#define MAX_ENT 150000

// ---------------- device scratch ----------------
__device__ float    g_nodesA[(size_t)MAX_N * D];
__device__ float    g_nodesB[(size_t)MAX_N * D];
__device__ float    g_hbuf  [(size_t)MAX_N * D];   // GAT: hcat rows (stride 256)
__device__ float    g_dinv  [MAX_N];
__device__ int      g_deg   [MAX_N];
__device__ int      g_off   [MAX_N];
__device__ int      g_cur   [MAX_N];
__device__ int      g_bsums [1024];
__device__ int      g_csrc  [MAX_E2];
__device__ int      g_offE  [MAX_ENT];
__device__ int      g_curE  [MAX_ENT];
__device__ int      g_bsumsE[1024];
__device__ float2   g_als2  [MAX_ENT];
__device__ float2   g_ald2  [MAX_ENT];
__device__ float2   g_eself2[MAX_ENT];
__device__ int      g_cnt   [MAX_ENT];
__device__ float    g_lattr [MAX_ENT];
__device__ int2     g_gsl   [MAX_E1];     // CSR payload: (src, label bits)
__device__ int      g_gdst  [MAX_E1];     // CSR slot -> dst
__device__ float4   g_gpe   [MAX_E1];     // packed: (src bits, e1, e2, pad)
__device__ float    g_ce2[2];
__device__ float    g_zerovec[D];
// pre-converted weights (bf16 hi/lo) + combined GAT weights/biases
__device__ __nv_bfloat16 g_w1hi[128*128],  g_w1lo[128*128];    // g1W
__device__ __nv_bfloat16 g_wc1hi[128*128], g_wc1lo[128*128];   // g2W@Wl1
__device__ __nv_bfloat16 g_wc2hi[128*128], g_wc2lo[128*128];   // g2W@Wl2
__device__ float    g_b1c[128], g_b2c[128];                    // g2b@Wl

// ---------------- small helpers ----------------
__device__ __forceinline__ float lrelu(float x){ return x > 0.f ? x : 0.2f * x; }
__device__ __forceinline__ uint32_t smem_u32(const void* p){
    uint32_t a; asm("{ .reg .u64 t; cvta.to.shared.u64 t, %1; cvt.u32.u64 %0, t; }" : "=r"(a) : "l"(p));
    return a;
}
__device__ __forceinline__ float4 f4axpy(float s, float4 a, float4 acc){
    acc.x += s*a.x; acc.y += s*a.y; acc.z += s*a.z; acc.w += s*a.w; return acc;
}

// ---------------- mma.sync bf16x3 GEMM (64-row M tiles) ----------------
#define ASTR   136
#define AS_HI  0u
#define AS_LO  17408u
#define BS_HI2 34816u
#define BS_LO2 69632u
#define SMEM_MMA 104448

__device__ __forceinline__ void ldsm4(uint32_t (&r)[4], uint32_t addr){
    asm volatile("ldmatrix.sync.aligned.m8n8.x4.shared.b16 {%0,%1,%2,%3}, [%4];"
        : "=r"(r[0]), "=r"(r[1]), "=r"(r[2]), "=r"(r[3]) : "r"(addr));
}
__device__ __forceinline__ void ldsm4t(uint32_t &r0, uint32_t &r1, uint32_t &r2, uint32_t &r3, uint32_t addr){
    asm volatile("ldmatrix.sync.aligned.m8n8.x4.trans.shared.b16 {%0,%1,%2,%3}, [%4];"
        : "=r"(r0), "=r"(r1), "=r"(r2), "=r"(r3) : "r"(addr));
}
__device__ __forceinline__ void mma_bf16(float (&d)[4], const uint32_t (&a)[4], uint32_t b0, uint32_t b1){
    asm volatile("mma.sync.aligned.m16n8k16.row.col.f32.bf16.bf16.f32 "
        "{%0,%1,%2,%3}, {%4,%5,%6,%7}, {%8,%9}, {%0,%1,%2,%3};"
        : "+f"(d[0]), "+f"(d[1]), "+f"(d[2]), "+f"(d[3])
        : "r"(a[0]), "r"(a[1]), "r"(a[2]), "r"(a[3]), "r"(b0), "r"(b1));
}
__device__ __forceinline__ uint32_t frag_addr(uint32_t arr, int row0, int col0, int lane){
    int grp = lane >> 3, lr = lane & 7;
    int r = row0 + (grp & 1)*8 + lr;
    int c = col0 + (grp >> 1)*8;
    return arr + (uint32_t)(r*ASTR + c)*2u;
}
__device__ __forceinline__ void stage4(char* sm, uint32_t off_hi, uint32_t off_lo,
                                       int r, int c4, float4 v){
    __nv_bfloat16 h0 = __float2bfloat16_rn(v.x), h1 = __float2bfloat16_rn(v.y),
                  h2 = __float2bfloat16_rn(v.z), h3 = __float2bfloat16_rn(v.w);
    __nv_bfloat16 l0 = __float2bfloat16_rn(v.x - __bfloat162float(h0));
    __nv_bfloat16 l1 = __float2bfloat16_rn(v.y - __bfloat162float(h1));
    __nv_bfloat16 l2 = __float2bfloat16_rn(v.z - __bfloat162float(h2));
    __nv_bfloat16 l3 = __float2bfloat16_rn(v.w - __bfloat162float(h3));
    __nv_bfloat162 hp0, hp1, lp0, lp1;
    hp0.x = h0; hp0.y = h1; hp1.x = h2; hp1.y = h3;
    lp0.x = l0; lp0.y = l1; lp1.x = l2; lp1.y = l3;
    uint32_t byt = (uint32_t)(r*ASTR + c4*4)*2u;
    uint2 uh, ul;
    uh.x = *(uint32_t*)&hp0; uh.y = *(uint32_t*)&hp1;
    ul.x = *(uint32_t*)&lp0; ul.y = *(uint32_t*)&lp1;
    *(uint2*)(sm + off_hi + byt) = uh;
    *(uint2*)(sm + off_lo + byt) = ul;
}

__device__ __forceinline__ void mma_slab64(uint32_t smb, int wm, int n0, int lane,
                                           float (&acc)[8][4]){
#pragma unroll
    for (int kt = 0; kt < 8; ++kt){
        int k0 = kt*16;
        uint32_t ah[4], al[4], bh[8][2], bl[8][2];
        uint32_t adr = frag_addr(smb + AS_HI, wm*16, k0, lane);
        ldsm4(ah, adr);
        ldsm4(al, adr + (AS_LO - AS_HI));
#pragma unroll
        for (int nb = 0; nb < 4; ++nb){
            uint32_t badr = frag_addr(smb + BS_HI2, k0, n0 + nb*16, lane);
            ldsm4t(bh[2*nb][0], bh[2*nb][1], bh[2*nb+1][0], bh[2*nb+1][1], badr);
            ldsm4t(bl[2*nb][0], bl[2*nb][1], bl[2*nb+1][0], bl[2*nb+1][1],
                   badr + (BS_LO2 - BS_HI2));
        }
#pragma unroll
        for (int nt = 0; nt < 8; ++nt){
            mma_bf16(acc[nt], ah, bh[nt][0], bh[nt][1]);
            mma_bf16(acc[nt], ah, bl[nt][0], bl[nt][1]);
            mma_bf16(acc[nt], al, bh[nt][0], bh[nt][1]);
        }
    }
}

// C = A @ B (+bias); B pre-converted bf16 hi/lo. Optional fused attention
// dot-products: als/ald (component comp of g_als2/g_ald2) = (C row) . asrc/adst.
__global__ void __launch_bounds__(256) k_gemm_pre(const float* __restrict__ Alow,
    const float* __restrict__ Ahigh, int split,
    const __nv_bfloat16* __restrict__ Bhi, const __nv_bfloat16* __restrict__ Blo,
    float* __restrict__ C, const float* __restrict__ bias, int ldc, int M,
    const float* __restrict__ asrc, const float* __restrict__ adst, int comp)
{
    extern __shared__ char sm[];
    const uint32_t smb = smem_u32(sm);
    const int tid = threadIdx.x, lane = tid & 31, wid = tid >> 5;
    const int wm = wid & 3, n0 = (wid >> 2)*64;
    const int m0 = blockIdx.x * 64;

#pragma unroll
    for (int i = 0; i < 8; ++i){
        int f = tid + i*256, r = f >> 5, c4 = f & 31;
        int row = m0 + r; if (row >= M) row = M - 1;
        const float* src = (row < split) ? (Alow + (size_t)row*D)
                                         : (Ahigh + (size_t)(row - split)*D);
        stage4(sm, AS_HI, AS_LO, r, c4, *(const float4*)(src + c4*4));
    }
#pragma unroll
    for (int i = 0; i < 8; ++i){
        int f = tid + i*256;
        int r = f >> 4, c = f & 15;
        uint32_t dst = (uint32_t)(r*(ASTR*2) + c*16);
        *(uint4*)(sm + BS_HI2 + dst) = ((const uint4*)Bhi)[f];
        *(uint4*)(sm + BS_LO2 + dst) = ((const uint4*)Blo)[f];
    }
    __syncthreads();

    float acc[8][4];
#pragma unroll
    for (int nt = 0; nt < 8; ++nt)
#pragma unroll
        for (int j = 0; j < 4; ++j) acc[nt][j] = 0.f;

    mma_slab64(smb, wm, n0, lane, acc);

#pragma unroll
    for (int nt = 0; nt < 8; ++nt){
        int c = n0 + nt*8 + (lane & 3)*2;
        float b0 = bias ? bias[c] : 0.f, b1v = bias ? bias[c+1] : 0.f;
        acc[nt][0] += b0; acc[nt][1] += b1v;
        acc[nt][2] += b0; acc[nt][3] += b1v;
        int r = m0 + wm*16 + (lane >> 2);
        if (r < M)
            *(float2*)(C + (size_t)r*ldc + c) = make_float2(acc[nt][0], acc[nt][1]);
        if (r + 8 < M)
            *(float2*)(C + (size_t)(r+8)*ldc + c) = make_float2(acc[nt][2], acc[nt][3]);
    }

    if (asrc){
        float* red = (float*)sm;   // [0..63]=als rows, [64..127]=ald rows
        __syncthreads();
        if (tid < 128) red[tid] = 0.f;
        __syncthreads();
        float pa = 0.f, pa8 = 0.f, pd = 0.f, pd8 = 0.f;
#pragma unroll
        for (int nt = 0; nt < 8; ++nt){
            int c = n0 + nt*8 + (lane & 3)*2;
            float s0 = asrc[c], s1 = asrc[c+1], t0 = adst[c], t1 = adst[c+1];
            pa  += acc[nt][0]*s0 + acc[nt][1]*s1;
            pa8 += acc[nt][2]*s0 + acc[nt][3]*s1;
            pd  += acc[nt][0]*t0 + acc[nt][1]*t1;
            pd8 += acc[nt][2]*t0 + acc[nt][3]*t1;
        }
#pragma unroll
        for (int o = 1; o <= 2; o <<= 1){
            pa  += __shfl_xor_sync(0xffffffffu, pa,  o);
            pa8 += __shfl_xor_sync(0xffffffffu, pa8, o);
            pd  += __shfl_xor_sync(0xffffffffu, pd,  o);
            pd8 += __shfl_xor_sync(0xffffffffu, pd8, o);
        }
        if ((lane & 3) == 0){
            int lr = wm*16 + (lane >> 2);
            atomicAdd(red + lr,          pa);
            atomicAdd(red + lr + 8,      pa8);
            atomicAdd(red + 64 + lr,     pd);
            atomicAdd(red + 64 + lr + 8, pd8);
        }
        __syncthreads();
        if (tid < 64 && m0 + tid < M){
            ((float*)g_als2)[(size_t)(m0 + tid)*2 + comp] = red[tid];
            ((float*)g_ald2)[(size_t)(m0 + tid)*2 + comp] = red[64 + tid];
        }
    }
}

// C[t,:] = concat(att[a_t], val[v_t]) @ W (K=256), on-the-fly B convert
__global__ void __launch_bounds__(256) k_valenc_mma(const int* __restrict__ triples,
    const float* __restrict__ att, const float* __restrict__ val,
    const float* __restrict__ W, float* __restrict__ C, int T)
{
    extern __shared__ char sm[];
    __shared__ int idxA[64], idxV[64];
    const uint32_t smb = smem_u32(sm);
    const int tid = threadIdx.x, lane = tid & 31, wid = tid >> 5;
    const int wm = wid & 3, n0 = (wid >> 2)*64;
    const int m0 = blockIdx.x * 64;
    if (tid < 64){
        int t = m0 + tid; if (t >= T) t = T - 1;
        idxV[tid] = triples[3*t + 1];
        idxA[tid] = triples[3*t + 2];
    }
    __syncthreads();

    float acc[8][4];
#pragma unroll
    for (int nt = 0; nt < 8; ++nt)
#pragma unroll
        for (int j = 0; j < 4; ++j) acc[nt][j] = 0.f;

    for (int ph = 0; ph < 2; ++ph){
        if (ph) __syncthreads();
#pragma unroll
        for (int i = 0; i < 8; ++i){
            int f = tid + i*256, r = f >> 5, c4 = f & 31;
            const float* src = ph ? (val + (size_t)idxV[r]*D) : (att + (size_t)idxA[r]*D);
            stage4(sm, AS_HI, AS_LO, r, c4, *(const float4*)(src + c4*4));
        }
        const float* Wph = W + (size_t)ph*128*D;
#pragma unroll
        for (int i = 0; i < 16; ++i){
            int f = tid + i*256, r = f >> 5, c4 = f & 31;
            stage4(sm, BS_HI2, BS_LO2, r, c4, *(const float4*)(Wph + (size_t)r*D + c4*4));
        }
        __syncthreads();
        mma_slab64(smb, wm, n0, lane, acc);
    }

#pragma unroll
    for (int nt = 0; nt < 8; ++nt){
        int r = m0 + wm*16 + (lane >> 2);
        int c = n0 + nt*8 + (lane & 3)*2;
        if (r < T)
            *(float2*)(C + (size_t)r*D + c) = make_float2(acc[nt][0], acc[nt][1]);
        if (r + 8 < T)
            *(float2*)(C + (size_t)(r+8)*D + c) = make_float2(acc[nt][2], acc[nt][3]);
    }
}

// ---------------- weight prep ----------------
__global__ void k_conv(const float* __restrict__ W, __nv_bfloat16* __restrict__ hi,
                       __nv_bfloat16* __restrict__ lo, int n4){
    int i = blockIdx.x*blockDim.x + threadIdx.x;
    if (i >= n4) return;
    float4 v = ((const float4*)W)[i];
    __nv_bfloat16 h0 = __float2bfloat16_rn(v.x), h1 = __float2bfloat16_rn(v.y),
                  h2 = __float2bfloat16_rn(v.z), h3 = __float2bfloat16_rn(v.w);
    hi[4*i]   = h0; hi[4*i+1] = h1; hi[4*i+2] = h2; hi[4*i+3] = h3;
    lo[4*i]   = __float2bfloat16_rn(v.x - __bfloat162float(h0));
    lo[4*i+1] = __float2bfloat16_rn(v.y - __bfloat162float(h1));
    lo[4*i+2] = __float2bfloat16_rn(v.z - __bfloat162float(h2));
    lo[4*i+3] = __float2bfloat16_rn(v.w - __bfloat162float(h3));
}
__global__ void __launch_bounds__(128) k_wcomb(const float* __restrict__ A,
    const float* __restrict__ B, const float* __restrict__ bvec,
    __nv_bfloat16* __restrict__ chi, __nv_bfloat16* __restrict__ clo,
    float* __restrict__ bc)
{
    __shared__ float Ar[128];
    int r = blockIdx.x, c = threadIdx.x;
    const float* row = (r < 128) ? (A + r*128) : bvec;
    Ar[c] = row[c];
    __syncthreads();
    float acc = 0.f;
#pragma unroll 8
    for (int k = 0; k < 128; ++k) acc += Ar[k]*B[k*128 + c];
    if (r < 128){
        __nv_bfloat16 h = __float2bfloat16_rn(acc);
        chi[r*128 + c] = h;
        clo[r*128 + c] = __float2bfloat16_rn(acc - __bfloat162float(h));
    } else {
        bc[c] = acc;
    }
}

// ---------------- scan ----------------
#define SCAN_B 1024
__global__ void k_scan1(const int* __restrict__ in, int* __restrict__ out,
                        int* __restrict__ bsums, int n){
    __shared__ int s[SCAN_B];
    int t = threadIdx.x, idx = blockIdx.x*SCAN_B + t;
    int v = (idx < n) ? in[idx] : 0;
    s[t] = v; __syncthreads();
    for (int o = 1; o < SCAN_B; o <<= 1){
        int x = (t >= o) ? s[t-o] : 0; __syncthreads();
        s[t] += x; __syncthreads();
    }
    if (idx < n) out[idx] = s[t] - v;
    if (t == SCAN_B-1) bsums[blockIdx.x] = s[t];
}
__global__ void k_scan2(int* __restrict__ bsums, int nb){
    __shared__ int s[SCAN_B];
    int t = threadIdx.x;
    int v = (t < nb) ? bsums[t] : 0;
    s[t] = v; __syncthreads();
    for (int o = 1; o < SCAN_B; o <<= 1){
        int x = (t >= o) ? s[t-o] : 0; __syncthreads();
        s[t] += x; __syncthreads();
    }
    if (t < nb) bsums[t] = s[t] - v;
}
__global__ void k_scan3v(int* __restrict__ off, const int* __restrict__ bsums,
                         int* __restrict__ cur, const int* __restrict__ deg,
                         float* __restrict__ dinv, int n){
    int idx = blockIdx.x*blockDim.x + threadIdx.x;
    if (idx < n){
        int o = off[idx] + bsums[idx >> 10];
        off[idx] = o; cur[idx] = o;
        dinv[idx] = rsqrtf((float)(deg[idx] + 1));
    }
}
__global__ void k_scan3e(int* __restrict__ off, const int* __restrict__ bsums,
                         int* __restrict__ cur, const int* __restrict__ cnt,
                         float* __restrict__ ls, int n){
    int idx = blockIdx.x*blockDim.x + threadIdx.x;
    if (idx < n){
        int o = off[idx] + bsums[idx >> 10];
        off[idx] = o; cur[idx] = o;
        ls[idx] = ls[idx] / fmaxf((float)cnt[idx], 1.f);
    }
}

// ---------------- elementwise / build kernels ----------------
__global__ void k_seti(int* p, int v, int n){
    int i = blockIdx.x*blockDim.x + threadIdx.x; if (i < n) p[i] = v;
}
__global__ void k_init_gat(int* __restrict__ cnt, float* __restrict__ ls, int n){
    int i = blockIdx.x*blockDim.x + threadIdx.x;
    if (i < n){ cnt[i] = 0; ls[i] = 0.f; }
}
__global__ void k_deg_acc(const int2* __restrict__ ed, int* deg, int E){
    int i = blockIdx.x*blockDim.x + threadIdx.x;
    if (i < E) atomicAdd(deg + ed[i].y, 1);
}
__global__ void k_scat_val(const int2* __restrict__ ed, int* cur, int* csrc, int E){
    int i = blockIdx.x*blockDim.x + threadIdx.x;
    if (i >= E) return;
    int2 sd = ed[i];
    int pos = atomicAdd(cur + sd.y, 1);
    csrc[pos] = sd.x;
}
// (src, label, dst) scatter into GAT CSR order — feature-independent (branch C)
__global__ void k_scat_gat(const int2* __restrict__ ed, const float* __restrict__ lab,
                           int* cur, int E){
    int i = blockIdx.x*blockDim.x + threadIdx.x;
    if (i >= E) return;
    int2 sd = ed[i];
    int pos = atomicAdd(cur + sd.y, 1);
    g_gsl[pos] = make_int2(sd.x, __float_as_int(lab[i]));
    g_gdst[pos] = sd.y;
}
// warp per dst; 2-way unrolled edge loop
__global__ void k_gcn_csr(const float* __restrict__ h, const float* __restrict__ dinv,
                          const float* __restrict__ b, float* __restrict__ out,
                          const int* __restrict__ off, const int* __restrict__ deg,
                          const int* __restrict__ csrc, int M)
{
    int g = blockIdx.x*blockDim.x + threadIdx.x;
    int lane = g & 31, d = g >> 5;
    if (d >= M) return;
    float did = dinv[d];
    float4 hv = ((const float4*)(h + (size_t)d*D))[lane];
    float4 acc = *(const float4*)(b + lane*4);
    acc = f4axpy(did*did, hv, acc);
    int e0 = off[d], n = deg[d];
    int e = e0, eend = e0 + n;
    for (; e + 1 < eend; e += 2){
        int s0 = csrc[e], s1 = csrc[e+1];
        float dv0 = dinv[s0], dv1 = dinv[s1];
        float4 x0 = ((const float4*)(h + (size_t)s0*D))[lane];
        float4 x1 = ((const float4*)(h + (size_t)s1*D))[lane];
        acc = f4axpy(dv0*did, x0, acc);
        acc = f4axpy(dv1*did, x1, acc);
    }
    if (e < eend){
        int s = csrc[e];
        float4 xv = ((const float4*)(h + (size_t)s*D))[lane];
        acc = f4axpy(dinv[s]*did, xv, acc);
    }
    ((float4*)(out + (size_t)d*D))[lane] = acc;
}
__global__ void k_cnt(const int2* __restrict__ ed, const float* __restrict__ lab,
                      int* cnt, float* ls, int E){
    int i = blockIdx.x*blockDim.x + threadIdx.x;
    if (i < E){ int d = ed[i].y; atomicAdd(cnt + d, 1); atomicAdd(ls + d, lab[i]); }
}
__global__ void k_ce2(const float* __restrict__ We1, const float* __restrict__ ae1,
                      const float* __restrict__ We2, const float* __restrict__ ae2){
    int t = threadIdx.x;
    int lane = t & 31, w = t >> 5;
    const float* We = w ? We2 : We1;
    const float* ae = w ? ae2 : ae1;
    float s = 0.f;
    for (int i = lane; i < D; i += 32) s += We[i]*ae[i];
#pragma unroll
    for (int o = 16; o; o >>= 1) s += __shfl_xor_sync(0xffffffffu, s, o);
    if (lane == 0) g_ce2[w] = s;
}
// self-loop exp (als/ald produced by GEMM epilogues)
__global__ void k_self_exp(const float* __restrict__ lattr, int n){
    int i = blockIdx.x*blockDim.x + threadIdx.x;
    if (i < n){
        float2 als = g_als2[i], ald = g_ald2[i];
        float la = lattr[i];
        g_eself2[i] = make_float2(__expf(lrelu(als.x + ald.x + la*g_ce2[0])),
                                  __expf(lrelu(als.y + ald.y + la*g_ce2[1])));
    }
}
// one thread per CSR slot: packed payload (src, e1, e2)
__global__ void k_alpha_e(int E){
    int i = blockIdx.x*blockDim.x + threadIdx.x;
    if (i >= E) return;
    int2 sl = g_gsl[i];
    int d = g_gdst[i];
    float lab = __int_as_float(sl.y);
    float2 als = g_als2[sl.x];
    float2 ald = g_ald2[d];
    float e1 = __expf(lrelu(als.x + ald.x + lab*g_ce2[0]));
    float e2 = __expf(lrelu(als.y + ald.y + lab*g_ce2[1]));
    g_gpe[i] = make_float4(__int_as_float(sl.x), e1, e2, 0.f);
}
// warp per dst, single pass; 4-way unrolled edge loop, packed 16B payload
__global__ void k_gat_csr(const float* __restrict__ hcat, const float4* __restrict__ ent,
                          const float* __restrict__ b1, const float* __restrict__ b2,
                          const int* __restrict__ off, const int* __restrict__ cnt,
                          float* __restrict__ out, int M)
{
    int g = blockIdx.x*blockDim.x + threadIdx.x;
    int lane = g & 31, d = g >> 5;
    if (d >= M) return;
    float2 es = g_eself2[d];
    const float4* hp = (const float4*)(hcat + (size_t)d*256);
    float4 h1v = hp[lane], h2v = hp[lane + 32];
    float z1 = es.x, z2 = es.y;
    float4 a1 = make_float4(es.x*h1v.x, es.x*h1v.y, es.x*h1v.z, es.x*h1v.w);
    float4 a2 = make_float4(es.y*h2v.x, es.y*h2v.y, es.y*h2v.z, es.y*h2v.w);
    int e0 = off[d], n = cnt[d];
    int e = e0, eend = e0 + n;
    for (; e + 3 < eend; e += 4){
        float4 p0 = g_gpe[e],   p1 = g_gpe[e+1];
        float4 p2 = g_gpe[e+2], p3 = g_gpe[e+3];
        const float4* sp0 = (const float4*)(hcat + (size_t)__float_as_int(p0.x)*256);
        const float4* sp1 = (const float4*)(hcat + (size_t)__float_as_int(p1.x)*256);
        const float4* sp2 = (const float4*)(hcat + (size_t)__float_as_int(p2.x)*256);
        const float4* sp3 = (const float4*)(hcat + (size_t)__float_as_int(p3.x)*256);
        float4 x10 = sp0[lane], x20 = sp0[lane + 32];
        float4 x11 = sp1[lane], x21 = sp1[lane + 32];
        float4 x12 = sp2[lane], x22 = sp2[lane + 32];
        float4 x13 = sp3[lane], x23 = sp3[lane + 32];
        a1 = f4axpy(p0.y, x10, a1); a2 = f4axpy(p0.z, x20, a2);
        a1 = f4axpy(p1.y, x11, a1); a2 = f4axpy(p1.z, x21, a2);
        a1 = f4axpy(p2.y, x12, a1); a2 = f4axpy(p2.z, x22, a2);
        a1 = f4axpy(p3.y, x13, a1); a2 = f4axpy(p3.z, x23, a2);
        z1 += p0.y + p1.y + p2.y + p3.y;
        z2 += p0.z + p1.z + p2.z + p3.z;
    }
    for (; e < eend; ++e){
        float4 p = g_gpe[e];
        const float4* sp = (const float4*)(hcat + (size_t)__float_as_int(p.x)*256);
        a1 = f4axpy(p.y, sp[lane], a1);
        a2 = f4axpy(p.z, sp[lane + 32], a2);
        z1 += p.y; z2 += p.z;
    }
    float i1 = 1.f/(z1 + 1e-16f), i2 = 1.f/(z2 + 1e-16f);
    float4 ev = ent[(size_t)d*32 + lane];
    float4 bv1 = *(const float4*)(b1 + lane*4);
    float4 bv2 = *(const float4*)(b2 + lane*4);
    float4 o;
    o.x = ev.x + bv1.x + bv2.x + i1*a1.x + i2*a2.x;
    o.y = ev.y + bv1.y + bv2.y + i1*a1.y + i2*a2.y;
    o.z = ev.z + bv1.z + bv2.z + i1*a1.z + i2*a2.z;
    o.w = ev.w + bv1.w + bv2.w + i1*a1.w + i2*a2.w;
    ((float4*)(out + (size_t)d*D))[lane] = o;
}

// ---------------- launcher ----------------
extern "C" void kernel_launch(void* const* d_in, const int* in_sizes, int n_in,
                              void* d_out, int out_size)
{
    const int*   triples  = (const int*)  d_in[0];
    const int2*  ent_ed   = (const int2*) d_in[1];
    const float* ent_lab  = (const float*)d_in[2];
    const int2*  val_ed   = (const int2*) d_in[3];
    const float* att      = (const float*)d_in[5];
    const float* valf     = (const float*)d_in[6];
    const float* entf     = (const float*)d_in[7];
    const float* Wp       = (const float*)d_in[8];
    const float* g1W      = (const float*)d_in[9];
    const float* g1b      = (const float*)d_in[10];
    const float* g2W      = (const float*)d_in[11];
    const float* g2b      = (const float*)d_in[12];
    const float* Wl1      = (const float*)d_in[13];
    const float* as1      = (const float*)d_in[14];
    const float* ad1      = (const float*)d_in[15];
    const float* We1      = (const float*)d_in[16];
    const float* ae1      = (const float*)d_in[17];
    const float* gb1      = (const float*)d_in[18];
    const float* Wl2      = (const float*)d_in[19];
    const float* as2      = (const float*)d_in[20];
    const float* ad2      = (const float*)d_in[21];
    const float* We2      = (const float*)d_in[22];
    const float* ae2      = (const float*)d_in[23];
    const float* gb2      = (const float*)d_in[24];

    const int T   = in_sizes[0] / 3;
    const int E1  = in_sizes[1] / 2;
    const int E2  = in_sizes[3] / 2;
    const int NE  = in_sizes[7] / D;
    const int N   = NE + T;
    float* out = (float*)d_out;

    float *nodesA, *nodesB, *hbuf, *dinv, *lattr, *zerov, *b1c, *b2c;
    int *deg, *cnt, *off, *cur, *bsums, *csrc, *offE, *curE, *bsumsE;
    __nv_bfloat16 *w1hi, *w1lo, *wc1hi, *wc1lo, *wc2hi, *wc2lo;
    cudaGetSymbolAddress((void**)&nodesA, g_nodesA);
    cudaGetSymbolAddress((void**)&nodesB, g_nodesB);
    cudaGetSymbolAddress((void**)&hbuf,   g_hbuf);
    cudaGetSymbolAddress((void**)&dinv,   g_dinv);
    cudaGetSymbolAddress((void**)&deg,    g_deg);
    cudaGetSymbolAddress((void**)&cnt,    g_cnt);
    cudaGetSymbolAddress((void**)&lattr,  g_lattr);
    cudaGetSymbolAddress((void**)&zerov,  g_zerovec);
    cudaGetSymbolAddress((void**)&off,    g_off);
    cudaGetSymbolAddress((void**)&cur,    g_cur);
    cudaGetSymbolAddress((void**)&bsums,  g_bsums);
    cudaGetSymbolAddress((void**)&csrc,   g_csrc);
    cudaGetSymbolAddress((void**)&offE,   g_offE);
    cudaGetSymbolAddress((void**)&curE,   g_curE);
    cudaGetSymbolAddress((void**)&bsumsE, g_bsumsE);
    cudaGetSymbolAddress((void**)&w1hi,   g_w1hi);
    cudaGetSymbolAddress((void**)&w1lo,   g_w1lo);
    cudaGetSymbolAddress((void**)&wc1hi,  g_wc1hi);
    cudaGetSymbolAddress((void**)&wc1lo,  g_wc1lo);
    cudaGetSymbolAddress((void**)&wc2hi,  g_wc2hi);
    cudaGetSymbolAddress((void**)&wc2lo,  g_wc2lo);
    cudaGetSymbolAddress((void**)&b1c,    g_b1c);
    cudaGetSymbolAddress((void**)&b2c,    g_b2c);

    cudaFuncSetAttribute(k_gemm_pre,   cudaFuncAttributeMaxDynamicSharedMemorySize, SMEM_MMA);
    cudaFuncSetAttribute(k_valenc_mma, cudaFuncAttributeMaxDynamicSharedMemorySize, SMEM_MMA);

    const int TB = 256;
    #define GRID1(n) (((n) + TB - 1) / TB)

    cudaStream_t sB, sC;
    cudaStreamCreateWithFlags(&sB, cudaStreamNonBlocking);
    cudaStreamCreateWithFlags(&sC, cudaStreamNonBlocking);
    cudaEvent_t eF, eB, eW, eWC, eC;
    cudaEventCreateWithFlags(&eF,  cudaEventDisableTiming);
    cudaEventCreateWithFlags(&eB,  cudaEventDisableTiming);
    cudaEventCreateWithFlags(&eW,  cudaEventDisableTiming);
    cudaEventCreateWithFlags(&eWC, cudaEventDisableTiming);
    cudaEventCreateWithFlags(&eC,  cudaEventDisableTiming);
    cudaEventRecord(eF, 0);
    cudaStreamWaitEvent(sB, eF, 0);
    cudaStreamWaitEvent(sC, eF, 0);

    // ---- branch B: val-edge CSR + dinv ----
    k_seti   <<<GRID1(N), TB, 0, sB>>>(deg, 0, N);
    k_deg_acc<<<GRID1(E2), TB, 0, sB>>>(val_ed, deg, E2);
    {
        int nb = (N + SCAN_B - 1)/SCAN_B;
        k_scan1<<<nb, SCAN_B, 0, sB>>>(deg, off, bsums, N);
        k_scan2<<<1, SCAN_B, 0, sB>>>(bsums, nb);
        k_scan3v<<<GRID1(N), TB, 0, sB>>>(off, bsums, cur, deg, dinv, N);
    }
    k_scat_val<<<GRID1(E2), TB, 0, sB>>>(val_ed, cur, csrc, E2);
    cudaEventRecord(eB, sB);

    // ---- branch C: weight prep + full GAT CSR (incl. payload) + lattr + ce2 ----
    k_conv <<<(128*128/4 + TB - 1)/TB, TB, 0, sC>>>(g1W, w1hi, w1lo, 128*128/4);
    cudaEventRecord(eW, sC);
    k_wcomb<<<129, 128, 0, sC>>>(g2W, Wl1, g2b, wc1hi, wc1lo, b1c);
    k_wcomb<<<129, 128, 0, sC>>>(g2W, Wl2, g2b, wc2hi, wc2lo, b2c);
    cudaEventRecord(eWC, sC);
    k_init_gat<<<GRID1(NE), TB, 0, sC>>>(cnt, lattr, NE);
    k_cnt     <<<GRID1(E1), TB, 0, sC>>>(ent_ed, ent_lab, cnt, lattr, E1);
    {
        int nb = (NE + SCAN_B - 1)/SCAN_B;
        k_scan1<<<nb, SCAN_B, 0, sC>>>(cnt, offE, bsumsE, NE);
        k_scan2<<<1, SCAN_B, 0, sC>>>(bsumsE, nb);
        k_scan3e<<<GRID1(NE), TB, 0, sC>>>(offE, bsumsE, curE, cnt, lattr, NE);
    }
    k_scat_gat<<<GRID1(E1), TB, 0, sC>>>(ent_ed, ent_lab, curE, E1);
    k_ce2<<<1, 64, 0, sC>>>(We1, ae1, We2, ae2);
    cudaEventRecord(eC, sC);

    // ---- main: value encoder, then GCN1 GEMM ----
    float* valfeat = nodesA + (size_t)NE*D;
    k_valenc_mma<<<(T + 63)/64, TB, SMEM_MMA>>>(triples, att, valf, Wp, valfeat, T);
    cudaStreamWaitEvent(0, eW, 0);
    k_gemm_pre<<<(N + 63)/64, TB, SMEM_MMA>>>(entf, valfeat, NE, w1hi, w1lo, hbuf,
                                              (const float*)0, D, N,
                                              (const float*)0, (const float*)0, 0);

    // join B: aggregation needs CSR + dinv
    cudaStreamWaitEvent(0, eB, 0);
    k_gcn_csr<<<GRID1(N*32), TB>>>(hbuf, dinv, g1b, nodesB, off, deg, csrc, N);
    k_gcn_csr<<<GRID1(NE*32), TB>>>(nodesB, dinv, zerov, nodesA, off, deg, csrc, NE);

    // ---- GAT projections (GCN2 folded); als/ald computed in epilogue ----
    float* hcat = hbuf;
    cudaStreamWaitEvent(0, eWC, 0);
    k_gemm_pre<<<(NE + 63)/64, TB, SMEM_MMA>>>(nodesA, nodesA, NE, wc1hi, wc1lo,
                                               hcat,       b1c, 256, NE, as1, ad1, 0);
    k_gemm_pre<<<(NE + 63)/64, TB, SMEM_MMA>>>(nodesA, nodesA, NE, wc2hi, wc2lo,
                                               hcat + 128, b2c, 256, NE, as2, ad2, 1);

    // join C: attention needs lattr/ce2/CSR(offE,cnt,gsl,gdst)
    cudaStreamWaitEvent(0, eC, 0);
    k_self_exp<<<GRID1(NE), TB>>>(lattr, NE);
    k_alpha_e <<<GRID1(E1), TB>>>(E1);
    k_gat_csr<<<GRID1(NE*32), TB>>>(hcat, (const float4*)entf, gb1, gb2,
                                    offE, cnt, out, NE);

    cudaEventDestroy(eF); cudaEventDestroy(eB); cudaEventDestroy(eW);
    cudaEventDestroy(eWC); cudaEventDestroy(eC);
    cudaStreamDestroy(sB); cudaStreamDestroy(sC);
    #undef GRID1
}

// round 16
// speedup vs baseline: 1.0570x; 1.0570x over previous
#include <cuda_runtime.h>
#include <cuda_bf16.h>
#include <math.h>
#include <stdint.h>

#define D 128
#define MAX_N   400000
#define MAX_E1  1000000
#define MAX_E2  500000
#define MAX_ENT 150000

// ---------------- device scratch ----------------
__device__ float    g_nodesA[(size_t)MAX_N * D];
__device__ float    g_nodesB[(size_t)MAX_N * D];
__device__ float    g_hbuf  [(size_t)MAX_N * D];   // GAT: bf16 hcat rows (256 bf16/row)
__device__ float    g_dinv  [MAX_N];
__device__ int      g_deg   [MAX_N];
__device__ int      g_off   [MAX_N];
__device__ int      g_cur   [MAX_N];
__device__ int      g_bsums [1024];
__device__ int      g_csrc  [MAX_E2];
__device__ int      g_offE  [MAX_ENT];
__device__ int      g_curE  [MAX_ENT];
__device__ int      g_bsumsE[1024];
__device__ float2   g_als2  [MAX_ENT];
__device__ float2   g_ald2  [MAX_ENT];
__device__ float2   g_eself2[MAX_ENT];
__device__ int      g_cnt   [MAX_ENT];
__device__ float    g_lattr [MAX_ENT];
__device__ int2     g_gsl   [MAX_E1];     // CSR payload: (src, label bits)
__device__ int      g_gdst  [MAX_E1];     // CSR slot -> dst
__device__ float4   g_gpe   [MAX_E1];     // packed: (src bits, e1, e2, pad)
__device__ float    g_ce2[2];
__device__ float    g_zerovec[D];
// pre-converted weights (bf16 hi/lo) + combined GAT weights/biases
__device__ __nv_bfloat16 g_w1hi[128*128],  g_w1lo[128*128];    // g1W
__device__ __nv_bfloat16 g_wc1hi[128*128], g_wc1lo[128*128];   // g2W@Wl1
__device__ __nv_bfloat16 g_wc2hi[128*128], g_wc2lo[128*128];   // g2W@Wl2
__device__ float    g_b1c[128], g_b2c[128];                    // g2b@Wl

// ---------------- small helpers ----------------
__device__ __forceinline__ float lrelu(float x){ return x > 0.f ? x : 0.2f * x; }
__device__ __forceinline__ uint32_t smem_u32(const void* p){
    uint32_t a; asm("{ .reg .u64 t; cvta.to.shared.u64 t, %1; cvt.u32.u64 %0, t; }" : "=r"(a) : "l"(p));
    return a;
}
__device__ __forceinline__ float4 f4axpy(float s, float4 a, float4 acc){
    acc.x += s*a.x; acc.y += s*a.y; acc.z += s*a.z; acc.w += s*a.w; return acc;
}
// 8 bf16 (uint4) -> 8 floats
__device__ __forceinline__ void b8tof(uint4 u, float (&f)[8]){
    const __nv_bfloat162* p = (const __nv_bfloat162*)&u;
    float2 a0 = __bfloat1622float2(p[0]);
    float2 a1 = __bfloat1622float2(p[1]);
    float2 a2 = __bfloat1622float2(p[2]);
    float2 a3 = __bfloat1622float2(p[3]);
    f[0]=a0.x; f[1]=a0.y; f[2]=a1.x; f[3]=a1.y;
    f[4]=a2.x; f[5]=a2.y; f[6]=a3.x; f[7]=a3.y;
}

// ---------------- mma.sync bf16x3 GEMM (64-row M tiles) ----------------
#define ASTR   136
#define AS_HI  0u
#define AS_LO  17408u
#define BS_HI2 34816u
#define BS_LO2 69632u
#define SMEM_MMA 104448

__device__ __forceinline__ void ldsm4(uint32_t (&r)[4], uint32_t addr){
    asm volatile("ldmatrix.sync.aligned.m8n8.x4.shared.b16 {%0,%1,%2,%3}, [%4];"
        : "=r"(r[0]), "=r"(r[1]), "=r"(r[2]), "=r"(r[3]) : "r"(addr));
}
__device__ __forceinline__ void ldsm4t(uint32_t &r0, uint32_t &r1, uint32_t &r2, uint32_t &r3, uint32_t addr){
    asm volatile("ldmatrix.sync.aligned.m8n8.x4.trans.shared.b16 {%0,%1,%2,%3}, [%4];"
        : "=r"(r0), "=r"(r1), "=r"(r2), "=r"(r3) : "r"(addr));
}
__device__ __forceinline__ void mma_bf16(float (&d)[4], const uint32_t (&a)[4], uint32_t b0, uint32_t b1){
    asm volatile("mma.sync.aligned.m16n8k16.row.col.f32.bf16.bf16.f32 "
        "{%0,%1,%2,%3}, {%4,%5,%6,%7}, {%8,%9}, {%0,%1,%2,%3};"
        : "+f"(d[0]), "+f"(d[1]), "+f"(d[2]), "+f"(d[3])
        : "r"(a[0]), "r"(a[1]), "r"(a[2]), "r"(a[3]), "r"(b0), "r"(b1));
}
__device__ __forceinline__ uint32_t frag_addr(uint32_t arr, int row0, int col0, int lane){
    int grp = lane >> 3, lr = lane & 7;
    int r = row0 + (grp & 1)*8 + lr;
    int c = col0 + (grp >> 1)*8;
    return arr + (uint32_t)(r*ASTR + c)*2u;
}
__device__ __forceinline__ void stage4(char* sm, uint32_t off_hi, uint32_t off_lo,
                                       int r, int c4, float4 v){
    __nv_bfloat16 h0 = __float2bfloat16_rn(v.x), h1 = __float2bfloat16_rn(v.y),
                  h2 = __float2bfloat16_rn(v.z), h3 = __float2bfloat16_rn(v.w);
    __nv_bfloat16 l0 = __float2bfloat16_rn(v.x - __bfloat162float(h0));
    __nv_bfloat16 l1 = __float2bfloat16_rn(v.y - __bfloat162float(h1));
    __nv_bfloat16 l2 = __float2bfloat16_rn(v.z - __bfloat162float(h2));
    __nv_bfloat16 l3 = __float2bfloat16_rn(v.w - __bfloat162float(h3));
    __nv_bfloat162 hp0, hp1, lp0, lp1;
    hp0.x = h0; hp0.y = h1; hp1.x = h2; hp1.y = h3;
    lp0.x = l0; lp0.y = l1; lp1.x = l2; lp1.y = l3;
    uint32_t byt = (uint32_t)(r*ASTR + c4*4)*2u;
    uint2 uh, ul;
    uh.x = *(uint32_t*)&hp0; uh.y = *(uint32_t*)&hp1;
    ul.x = *(uint32_t*)&lp0; ul.y = *(uint32_t*)&lp1;
    *(uint2*)(sm + off_hi + byt) = uh;
    *(uint2*)(sm + off_lo + byt) = ul;
}

__device__ __forceinline__ void mma_slab64(uint32_t smb, int wm, int n0, int lane,
                                           float (&acc)[8][4]){
#pragma unroll
    for (int kt = 0; kt < 8; ++kt){
        int k0 = kt*16;
        uint32_t ah[4], al[4], bh[8][2], bl[8][2];
        uint32_t adr = frag_addr(smb + AS_HI, wm*16, k0, lane);
        ldsm4(ah, adr);
        ldsm4(al, adr + (AS_LO - AS_HI));
#pragma unroll
        for (int nb = 0; nb < 4; ++nb){
            uint32_t badr = frag_addr(smb + BS_HI2, k0, n0 + nb*16, lane);
            ldsm4t(bh[2*nb][0], bh[2*nb][1], bh[2*nb+1][0], bh[2*nb+1][1], badr);
            ldsm4t(bl[2*nb][0], bl[2*nb][1], bl[2*nb+1][0], bl[2*nb+1][1],
                   badr + (BS_LO2 - BS_HI2));
        }
#pragma unroll
        for (int nt = 0; nt < 8; ++nt){
            mma_bf16(acc[nt], ah, bh[nt][0], bh[nt][1]);
            mma_bf16(acc[nt], ah, bl[nt][0], bl[nt][1]);
            mma_bf16(acc[nt], al, bh[nt][0], bh[nt][1]);
        }
    }
}

// C = A @ B (+bias); B pre-converted bf16 hi/lo.
// If obf != 0: store bf16 into obf (row stride 256 bf16, column offset ocol).
// Optional fused attention dots into g_als2/g_ald2 component comp.
__global__ void __launch_bounds__(256) k_gemm_pre(const float* __restrict__ Alow,
    const float* __restrict__ Ahigh, int split,
    const __nv_bfloat16* __restrict__ Bhi, const __nv_bfloat16* __restrict__ Blo,
    float* __restrict__ C, const float* __restrict__ bias, int ldc, int M,
    __nv_bfloat16* __restrict__ obf, int ocol,
    const float* __restrict__ asrc, const float* __restrict__ adst, int comp)
{
    extern __shared__ char sm[];
    const uint32_t smb = smem_u32(sm);
    const int tid = threadIdx.x, lane = tid & 31, wid = tid >> 5;
    const int wm = wid & 3, n0 = (wid >> 2)*64;
    const int m0 = blockIdx.x * 64;

#pragma unroll
    for (int i = 0; i < 8; ++i){
        int f = tid + i*256, r = f >> 5, c4 = f & 31;
        int row = m0 + r; if (row >= M) row = M - 1;
        const float* src = (row < split) ? (Alow + (size_t)row*D)
                                         : (Ahigh + (size_t)(row - split)*D);
        stage4(sm, AS_HI, AS_LO, r, c4, *(const float4*)(src + c4*4));
    }
#pragma unroll
    for (int i = 0; i < 8; ++i){
        int f = tid + i*256;
        int r = f >> 4, c = f & 15;
        uint32_t dst = (uint32_t)(r*(ASTR*2) + c*16);
        *(uint4*)(sm + BS_HI2 + dst) = ((const uint4*)Bhi)[f];
        *(uint4*)(sm + BS_LO2 + dst) = ((const uint4*)Blo)[f];
    }
    __syncthreads();

    float acc[8][4];
#pragma unroll
    for (int nt = 0; nt < 8; ++nt)
#pragma unroll
        for (int j = 0; j < 4; ++j) acc[nt][j] = 0.f;

    mma_slab64(smb, wm, n0, lane, acc);

#pragma unroll
    for (int nt = 0; nt < 8; ++nt){
        int c = n0 + nt*8 + (lane & 3)*2;
        float b0 = bias ? bias[c] : 0.f, b1v = bias ? bias[c+1] : 0.f;
        acc[nt][0] += b0; acc[nt][1] += b1v;
        acc[nt][2] += b0; acc[nt][3] += b1v;
        int r = m0 + wm*16 + (lane >> 2);
        if (obf){
            __nv_bfloat162 v0, v1;
            v0.x = __float2bfloat16_rn(acc[nt][0]); v0.y = __float2bfloat16_rn(acc[nt][1]);
            v1.x = __float2bfloat16_rn(acc[nt][2]); v1.y = __float2bfloat16_rn(acc[nt][3]);
            if (r < M)
                *(uint32_t*)(obf + (size_t)r*256 + ocol + c) = *(uint32_t*)&v0;
            if (r + 8 < M)
                *(uint32_t*)(obf + (size_t)(r+8)*256 + ocol + c) = *(uint32_t*)&v1;
        } else {
            if (r < M)
                *(float2*)(C + (size_t)r*ldc + c) = make_float2(acc[nt][0], acc[nt][1]);
            if (r + 8 < M)
                *(float2*)(C + (size_t)(r+8)*ldc + c) = make_float2(acc[nt][2], acc[nt][3]);
        }
    }

    if (asrc){
        float* red = (float*)sm;   // [0..63]=als rows, [64..127]=ald rows
        __syncthreads();
        if (tid < 128) red[tid] = 0.f;
        __syncthreads();
        float pa = 0.f, pa8 = 0.f, pd = 0.f, pd8 = 0.f;
#pragma unroll
        for (int nt = 0; nt < 8; ++nt){
            int c = n0 + nt*8 + (lane & 3)*2;
            float s0 = asrc[c], s1 = asrc[c+1], t0 = adst[c], t1 = adst[c+1];
            pa  += acc[nt][0]*s0 + acc[nt][1]*s1;
            pa8 += acc[nt][2]*s0 + acc[nt][3]*s1;
            pd  += acc[nt][0]*t0 + acc[nt][1]*t1;
            pd8 += acc[nt][2]*t0 + acc[nt][3]*t1;
        }
#pragma unroll
        for (int o = 1; o <= 2; o <<= 1){
            pa  += __shfl_xor_sync(0xffffffffu, pa,  o);
            pa8 += __shfl_xor_sync(0xffffffffu, pa8, o);
            pd  += __shfl_xor_sync(0xffffffffu, pd,  o);
            pd8 += __shfl_xor_sync(0xffffffffu, pd8, o);
        }
        if ((lane & 3) == 0){
            int lr = wm*16 + (lane >> 2);
            atomicAdd(red + lr,          pa);
            atomicAdd(red + lr + 8,      pa8);
            atomicAdd(red + 64 + lr,     pd);
            atomicAdd(red + 64 + lr + 8, pd8);
        }
        __syncthreads();
        if (tid < 64 && m0 + tid < M){
            ((float*)g_als2)[(size_t)(m0 + tid)*2 + comp] = red[tid];
            ((float*)g_ald2)[(size_t)(m0 + tid)*2 + comp] = red[64 + tid];
        }
    }
}

// C[t,:] = concat(att[a_t], val[v_t]) @ W (K=256), on-the-fly B convert
__global__ void __launch_bounds__(256) k_valenc_mma(const int* __restrict__ triples,
    const float* __restrict__ att, const float* __restrict__ val,
    const float* __restrict__ W, float* __restrict__ C, int T)
{
    extern __shared__ char sm[];
    __shared__ int idxA[64], idxV[64];
    const uint32_t smb = smem_u32(sm);
    const int tid = threadIdx.x, lane = tid & 31, wid = tid >> 5;
    const int wm = wid & 3, n0 = (wid >> 2)*64;
    const int m0 = blockIdx.x * 64;
    if (tid < 64){
        int t = m0 + tid; if (t >= T) t = T - 1;
        idxV[tid] = triples[3*t + 1];
        idxA[tid] = triples[3*t + 2];
    }
    __syncthreads();

    float acc[8][4];
#pragma unroll
    for (int nt = 0; nt < 8; ++nt)
#pragma unroll
        for (int j = 0; j < 4; ++j) acc[nt][j] = 0.f;

    for (int ph = 0; ph < 2; ++ph){
        if (ph) __syncthreads();
#pragma unroll
        for (int i = 0; i < 8; ++i){
            int f = tid + i*256, r = f >> 5, c4 = f & 31;
            const float* src = ph ? (val + (size_t)idxV[r]*D) : (att + (size_t)idxA[r]*D);
            stage4(sm, AS_HI, AS_LO, r, c4, *(const float4*)(src + c4*4));
        }
        const float* Wph = W + (size_t)ph*128*D;
#pragma unroll
        for (int i = 0; i < 16; ++i){
            int f = tid + i*256, r = f >> 5, c4 = f & 31;
            stage4(sm, BS_HI2, BS_LO2, r, c4, *(const float4*)(Wph + (size_t)r*D + c4*4));
        }
        __syncthreads();
        mma_slab64(smb, wm, n0, lane, acc);
    }

#pragma unroll
    for (int nt = 0; nt < 8; ++nt){
        int r = m0 + wm*16 + (lane >> 2);
        int c = n0 + nt*8 + (lane & 3)*2;
        if (r < T)
            *(float2*)(C + (size_t)r*D + c) = make_float2(acc[nt][0], acc[nt][1]);
        if (r + 8 < T)
            *(float2*)(C + (size_t)(r+8)*D + c) = make_float2(acc[nt][2], acc[nt][3]);
    }
}

// ---------------- weight prep ----------------
__global__ void k_conv(const float* __restrict__ W, __nv_bfloat16* __restrict__ hi,
                       __nv_bfloat16* __restrict__ lo, int n4){
    int i = blockIdx.x*blockDim.x + threadIdx.x;
    if (i >= n4) return;
    float4 v = ((const float4*)W)[i];
    __nv_bfloat16 h0 = __float2bfloat16_rn(v.x), h1 = __float2bfloat16_rn(v.y),
                  h2 = __float2bfloat16_rn(v.z), h3 = __float2bfloat16_rn(v.w);
    hi[4*i]   = h0; hi[4*i+1] = h1; hi[4*i+2] = h2; hi[4*i+3] = h3;
    lo[4*i]   = __float2bfloat16_rn(v.x - __bfloat162float(h0));
    lo[4*i+1] = __float2bfloat16_rn(v.y - __bfloat162float(h1));
    lo[4*i+2] = __float2bfloat16_rn(v.z - __bfloat162float(h2));
    lo[4*i+3] = __float2bfloat16_rn(v.w - __bfloat162float(h3));
}
__global__ void __launch_bounds__(128) k_wcomb(const float* __restrict__ A,
    const float* __restrict__ B, const float* __restrict__ bvec,
    __nv_bfloat16* __restrict__ chi, __nv_bfloat16* __restrict__ clo,
    float* __restrict__ bc)
{
    __shared__ float Ar[128];
    int r = blockIdx.x, c = threadIdx.x;
    const float* row = (r < 128) ? (A + r*128) : bvec;
    Ar[c] = row[c];
    __syncthreads();
    float acc = 0.f;
#pragma unroll 8
    for (int k = 0; k < 128; ++k) acc += Ar[k]*B[k*128 + c];
    if (r < 128){
        __nv_bfloat16 h = __float2bfloat16_rn(acc);
        chi[r*128 + c] = h;
        clo[r*128 + c] = __float2bfloat16_rn(acc - __bfloat162float(h));
    } else {
        bc[c] = acc;
    }
}

// ---------------- scan ----------------
#define SCAN_B 1024
__global__ void k_scan1(const int* __restrict__ in, int* __restrict__ out,
                        int* __restrict__ bsums, int n){
    __shared__ int s[SCAN_B];
    int t = threadIdx.x, idx = blockIdx.x*SCAN_B + t;
    int v = (idx < n) ? in[idx] : 0;
    s[t] = v; __syncthreads();
    for (int o = 1; o < SCAN_B; o <<= 1){
        int x = (t >= o) ? s[t-o] : 0; __syncthreads();
        s[t] += x; __syncthreads();
    }
    if (idx < n) out[idx] = s[t] - v;
    if (t == SCAN_B-1) bsums[blockIdx.x] = s[t];
}
__global__ void k_scan2(int* __restrict__ bsums, int nb){
    __shared__ int s[SCAN_B];
    int t = threadIdx.x;
    int v = (t < nb) ? bsums[t] : 0;
    s[t] = v; __syncthreads();
    for (int o = 1; o < SCAN_B; o <<= 1){
        int x = (t >= o) ? s[t-o] : 0; __syncthreads();
        s[t] += x; __syncthreads();
    }
    if (t < nb) bsums[t] = s[t] - v;
}
__global__ void k_scan3v(int* __restrict__ off, const int* __restrict__ bsums,
                         int* __restrict__ cur, const int* __restrict__ deg,
                         float* __restrict__ dinv, int n){
    int idx = blockIdx.x*blockDim.x + threadIdx.x;
    if (idx < n){
        int o = off[idx] + bsums[idx >> 10];
        off[idx] = o; cur[idx] = o;
        dinv[idx] = rsqrtf((float)(deg[idx] + 1));
    }
}
__global__ void k_scan3e(int* __restrict__ off, const int* __restrict__ bsums,
                         int* __restrict__ cur, const int* __restrict__ cnt,
                         float* __restrict__ ls, int n){
    int idx = blockIdx.x*blockDim.x + threadIdx.x;
    if (idx < n){
        int o = off[idx] + bsums[idx >> 10];
        off[idx] = o; cur[idx] = o;
        ls[idx] = ls[idx] / fmaxf((float)cnt[idx], 1.f);
    }
}

// ---------------- elementwise / build kernels ----------------
__global__ void k_seti(int* p, int v, int n){
    int i = blockIdx.x*blockDim.x + threadIdx.x; if (i < n) p[i] = v;
}
__global__ void k_init_gat(int* __restrict__ cnt, float* __restrict__ ls, int n){
    int i = blockIdx.x*blockDim.x + threadIdx.x;
    if (i < n){ cnt[i] = 0; ls[i] = 0.f; }
}
__global__ void k_deg_acc(const int2* __restrict__ ed, int* deg, int E){
    int i = blockIdx.x*blockDim.x + threadIdx.x;
    if (i < E) atomicAdd(deg + ed[i].y, 1);
}
__global__ void k_scat_val(const int2* __restrict__ ed, int* cur, int* csrc, int E){
    int i = blockIdx.x*blockDim.x + threadIdx.x;
    if (i >= E) return;
    int2 sd = ed[i];
    int pos = atomicAdd(cur + sd.y, 1);
    csrc[pos] = sd.x;
}
__global__ void k_scat_gat(const int2* __restrict__ ed, const float* __restrict__ lab,
                           int* cur, int E){
    int i = blockIdx.x*blockDim.x + threadIdx.x;
    if (i >= E) return;
    int2 sd = ed[i];
    int pos = atomicAdd(cur + sd.y, 1);
    g_gsl[pos] = make_int2(sd.x, __float_as_int(lab[i]));
    g_gdst[pos] = sd.y;
}
// warp per dst; 2-way unrolled edge loop (fp32 features)
__global__ void k_gcn_csr(const float* __restrict__ h, const float* __restrict__ dinv,
                          const float* __restrict__ b, float* __restrict__ out,
                          const int* __restrict__ off, const int* __restrict__ deg,
                          const int* __restrict__ csrc, int M)
{
    int g = blockIdx.x*blockDim.x + threadIdx.x;
    int lane = g & 31, d = g >> 5;
    if (d >= M) return;
    float did = dinv[d];
    float4 hv = ((const float4*)(h + (size_t)d*D))[lane];
    float4 acc = *(const float4*)(b + lane*4);
    acc = f4axpy(did*did, hv, acc);
    int e0 = off[d], n = deg[d];
    int e = e0, eend = e0 + n;
    for (; e + 1 < eend; e += 2){
        int s0 = csrc[e], s1 = csrc[e+1];
        float dv0 = dinv[s0], dv1 = dinv[s1];
        float4 x0 = ((const float4*)(h + (size_t)s0*D))[lane];
        float4 x1 = ((const float4*)(h + (size_t)s1*D))[lane];
        acc = f4axpy(dv0*did, x0, acc);
        acc = f4axpy(dv1*did, x1, acc);
    }
    if (e < eend){
        int s = csrc[e];
        float4 xv = ((const float4*)(h + (size_t)s*D))[lane];
        acc = f4axpy(dinv[s]*did, xv, acc);
    }
    ((float4*)(out + (size_t)d*D))[lane] = acc;
}
__global__ void k_cnt(const int2* __restrict__ ed, const float* __restrict__ lab,
                      int* cnt, float* ls, int E){
    int i = blockIdx.x*blockDim.x + threadIdx.x;
    if (i < E){ int d = ed[i].y; atomicAdd(cnt + d, 1); atomicAdd(ls + d, lab[i]); }
}
__global__ void k_ce2(const float* __restrict__ We1, const float* __restrict__ ae1,
                      const float* __restrict__ We2, const float* __restrict__ ae2){
    int t = threadIdx.x;
    int lane = t & 31, w = t >> 5;
    const float* We = w ? We2 : We1;
    const float* ae = w ? ae2 : ae1;
    float s = 0.f;
    for (int i = lane; i < D; i += 32) s += We[i]*ae[i];
#pragma unroll
    for (int o = 16; o; o >>= 1) s += __shfl_xor_sync(0xffffffffu, s, o);
    if (lane == 0) g_ce2[w] = s;
}
__global__ void k_self_exp(const float* __restrict__ lattr, int n){
    int i = blockIdx.x*blockDim.x + threadIdx.x;
    if (i < n){
        float2 als = g_als2[i], ald = g_ald2[i];
        float la = lattr[i];
        g_eself2[i] = make_float2(__expf(lrelu(als.x + ald.x + la*g_ce2[0])),
                                  __expf(lrelu(als.y + ald.y + la*g_ce2[1])));
    }
}
__global__ void k_alpha_e(int E){
    int i = blockIdx.x*blockDim.x + threadIdx.x;
    if (i >= E) return;
    int2 sl = g_gsl[i];
    int d = g_gdst[i];
    float lab = __int_as_float(sl.y);
    float2 als = g_als2[sl.x];
    float2 ald = g_ald2[d];
    float e1 = __expf(lrelu(als.x + ald.x + lab*g_ce2[0]));
    float e2 = __expf(lrelu(als.y + ald.y + lab*g_ce2[1]));
    g_gpe[i] = make_float4(__int_as_float(sl.x), e1, e2, 0.f);
}
// warp per dst over bf16 hcat: lane<16 -> 8 h1-cols, lane>=16 -> 8 h2-cols.
// One 16B load per lane per edge. Layers combined via shfl at the end.
__global__ void k_gat_csr(const __nv_bfloat16* __restrict__ hcat,
                          const float* __restrict__ ent,
                          const float* __restrict__ b1, const float* __restrict__ b2,
                          const int* __restrict__ off, const int* __restrict__ cnt,
                          float* __restrict__ out, int M)
{
    int g = blockIdx.x*blockDim.x + threadIdx.x;
    int lane = g & 31, d = g >> 5;
    if (d >= M) return;
    float2 es = g_eself2[d];
    float wself = (lane < 16) ? es.x : es.y;
    const uint4* hrow = (const uint4*)(hcat + (size_t)d*256);
    float hv[8]; b8tof(hrow[lane], hv);
    float acc[8];
#pragma unroll
    for (int j = 0; j < 8; ++j) acc[j] = wself*hv[j];
    float z1 = es.x, z2 = es.y;
    int e0 = off[d], n = cnt[d];
    int e = e0, eend = e0 + n;
    for (; e + 1 < eend; e += 2){
        float4 p0 = g_gpe[e], p1 = g_gpe[e+1];
        const uint4* r0 = (const uint4*)(hcat + (size_t)__float_as_int(p0.x)*256);
        const uint4* r1 = (const uint4*)(hcat + (size_t)__float_as_int(p1.x)*256);
        uint4 u0 = r0[lane], u1 = r1[lane];
        float w0 = (lane < 16) ? p0.y : p0.z;
        float w1 = (lane < 16) ? p1.y : p1.z;
        float x0[8], x1[8];
        b8tof(u0, x0); b8tof(u1, x1);
#pragma unroll
        for (int j = 0; j < 8; ++j) acc[j] += w0*x0[j] + w1*x1[j];
        z1 += p0.y + p1.y; z2 += p0.z + p1.z;
    }
    if (e < eend){
        float4 p = g_gpe[e];
        const uint4* r = (const uint4*)(hcat + (size_t)__float_as_int(p.x)*256);
        uint4 u = r[lane];
        float w = (lane < 16) ? p.y : p.z;
        float x[8]; b8tof(u, x);
#pragma unroll
        for (int j = 0; j < 8; ++j) acc[j] += w*x[j];
        z1 += p.y; z2 += p.z;
    }
    float i1 = 1.f/(z1 + 1e-16f), i2 = 1.f/(z2 + 1e-16f);
    float wn = (lane < 16) ? i1 : i2;
#pragma unroll
    for (int j = 0; j < 8; ++j) acc[j] *= wn;
    // lanes 0-15 collect layer-2 partials from lanes 16-31
    float oth[8];
#pragma unroll
    for (int j = 0; j < 8; ++j)
        oth[j] = __shfl_down_sync(0xffffffffu, acc[j], 16);
    if (lane < 16){
        int c0 = lane*8;
        const float* ep = ent + (size_t)d*D + c0;
        float4 e1v = *(const float4*)(ep);
        float4 e2v = *(const float4*)(ep + 4);
        float4 q1 = *(const float4*)(b1 + c0);
        float4 q2 = *(const float4*)(b1 + c0 + 4);
        float4 r1v = *(const float4*)(b2 + c0);
        float4 r2v = *(const float4*)(b2 + c0 + 4);
        float* op = out + (size_t)d*D + c0;
        *(float4*)(op) = make_float4(
            e1v.x + q1.x + r1v.x + acc[0] + oth[0],
            e1v.y + q1.y + r1v.y + acc[1] + oth[1],
            e1v.z + q1.z + r1v.z + acc[2] + oth[2],
            e1v.w + q1.w + r1v.w + acc[3] + oth[3]);
        *(float4*)(op + 4) = make_float4(
            e2v.x + q2.x + r2v.x + acc[4] + oth[4],
            e2v.y + q2.y + r2v.y + acc[5] + oth[5],
            e2v.z + q2.z + r2v.z + acc[6] + oth[6],
            e2v.w + q2.w + r2v.w + acc[7] + oth[7]);
    }
}

// ---------------- launcher ----------------
extern "C" void kernel_launch(void* const* d_in, const int* in_sizes, int n_in,
                              void* d_out, int out_size)
{
    const int*   triples  = (const int*)  d_in[0];
    const int2*  ent_ed   = (const int2*) d_in[1];
    const float* ent_lab  = (const float*)d_in[2];
    const int2*  val_ed   = (const int2*) d_in[3];
    const float* att      = (const float*)d_in[5];
    const float* valf     = (const float*)d_in[6];
    const float* entf     = (const float*)d_in[7];
    const float* Wp       = (const float*)d_in[8];
    const float* g1W      = (const float*)d_in[9];
    const float* g1b      = (const float*)d_in[10];
    const float* g2W      = (const float*)d_in[11];
    const float* g2b      = (const float*)d_in[12];
    const float* Wl1      = (const float*)d_in[13];
    const float* as1      = (const float*)d_in[14];
    const float* ad1      = (const float*)d_in[15];
    const float* We1      = (const float*)d_in[16];
    const float* ae1      = (const float*)d_in[17];
    const float* gb1      = (const float*)d_in[18];
    const float* Wl2      = (const float*)d_in[19];
    const float* as2      = (const float*)d_in[20];
    const float* ad2      = (const float*)d_in[21];
    const float* We2      = (const float*)d_in[22];
    const float* ae2      = (const float*)d_in[23];
    const float* gb2      = (const float*)d_in[24];

    const int T   = in_sizes[0] / 3;
    const int E1  = in_sizes[1] / 2;
    const int E2  = in_sizes[3] / 2;
    const int NE  = in_sizes[7] / D;
    const int N   = NE + T;
    float* out = (float*)d_out;

    float *nodesA, *nodesB, *hbuf, *dinv, *lattr, *zerov, *b1c, *b2c;
    int *deg, *cnt, *off, *cur, *bsums, *csrc, *offE, *curE, *bsumsE;
    __nv_bfloat16 *w1hi, *w1lo, *wc1hi, *wc1lo, *wc2hi, *wc2lo;
    cudaGetSymbolAddress((void**)&nodesA, g_nodesA);
    cudaGetSymbolAddress((void**)&nodesB, g_nodesB);
    cudaGetSymbolAddress((void**)&hbuf,   g_hbuf);
    cudaGetSymbolAddress((void**)&dinv,   g_dinv);
    cudaGetSymbolAddress((void**)&deg,    g_deg);
    cudaGetSymbolAddress((void**)&cnt,    g_cnt);
    cudaGetSymbolAddress((void**)&lattr,  g_lattr);
    cudaGetSymbolAddress((void**)&zerov,  g_zerovec);
    cudaGetSymbolAddress((void**)&off,    g_off);
    cudaGetSymbolAddress((void**)&cur,    g_cur);
    cudaGetSymbolAddress((void**)&bsums,  g_bsums);
    cudaGetSymbolAddress((void**)&csrc,   g_csrc);
    cudaGetSymbolAddress((void**)&offE,   g_offE);
    cudaGetSymbolAddress((void**)&curE,   g_curE);
    cudaGetSymbolAddress((void**)&bsumsE, g_bsumsE);
    cudaGetSymbolAddress((void**)&w1hi,   g_w1hi);
    cudaGetSymbolAddress((void**)&w1lo,   g_w1lo);
    cudaGetSymbolAddress((void**)&wc1hi,  g_wc1hi);
    cudaGetSymbolAddress((void**)&wc1lo,  g_wc1lo);
    cudaGetSymbolAddress((void**)&wc2hi,  g_wc2hi);
    cudaGetSymbolAddress((void**)&wc2lo,  g_wc2lo);
    cudaGetSymbolAddress((void**)&b1c,    g_b1c);
    cudaGetSymbolAddress((void**)&b2c,    g_b2c);

    cudaFuncSetAttribute(k_gemm_pre,   cudaFuncAttributeMaxDynamicSharedMemorySize, SMEM_MMA);
    cudaFuncSetAttribute(k_valenc_mma, cudaFuncAttributeMaxDynamicSharedMemorySize, SMEM_MMA);

    const int TB = 256;
    #define GRID1(n) (((n) + TB - 1) / TB)

    cudaStream_t sB, sC;
    cudaStreamCreateWithFlags(&sB, cudaStreamNonBlocking);
    cudaStreamCreateWithFlags(&sC, cudaStreamNonBlocking);
    cudaEvent_t eF, eB, eW, eWC, eC;
    cudaEventCreateWithFlags(&eF,  cudaEventDisableTiming);
    cudaEventCreateWithFlags(&eB,  cudaEventDisableTiming);
    cudaEventCreateWithFlags(&eW,  cudaEventDisableTiming);
    cudaEventCreateWithFlags(&eWC, cudaEventDisableTiming);
    cudaEventCreateWithFlags(&eC,  cudaEventDisableTiming);
    cudaEventRecord(eF, 0);
    cudaStreamWaitEvent(sB, eF, 0);
    cudaStreamWaitEvent(sC, eF, 0);

    // ---- branch B: val-edge CSR + dinv ----
    k_seti   <<<GRID1(N), TB, 0, sB>>>(deg, 0, N);
    k_deg_acc<<<GRID1(E2), TB, 0, sB>>>(val_ed, deg, E2);
    {
        int nb = (N + SCAN_B - 1)/SCAN_B;
        k_scan1<<<nb, SCAN_B, 0, sB>>>(deg, off, bsums, N);
        k_scan2<<<1, SCAN_B, 0, sB>>>(bsums, nb);
        k_scan3v<<<GRID1(N), TB, 0, sB>>>(off, bsums, cur, deg, dinv, N);
    }
    k_scat_val<<<GRID1(E2), TB, 0, sB>>>(val_ed, cur, csrc, E2);
    cudaEventRecord(eB, sB);

    // ---- branch C: weight prep + full GAT CSR (incl. payload) + lattr + ce2 ----
    k_conv <<<(128*128/4 + TB - 1)/TB, TB, 0, sC>>>(g1W, w1hi, w1lo, 128*128/4);
    cudaEventRecord(eW, sC);
    k_wcomb<<<129, 128, 0, sC>>>(g2W, Wl1, g2b, wc1hi, wc1lo, b1c);
    k_wcomb<<<129, 128, 0, sC>>>(g2W, Wl2, g2b, wc2hi, wc2lo, b2c);
    cudaEventRecord(eWC, sC);
    k_init_gat<<<GRID1(NE), TB, 0, sC>>>(cnt, lattr, NE);
    k_cnt     <<<GRID1(E1), TB, 0, sC>>>(ent_ed, ent_lab, cnt, lattr, E1);
    {
        int nb = (NE + SCAN_B - 1)/SCAN_B;
        k_scan1<<<nb, SCAN_B, 0, sC>>>(cnt, offE, bsumsE, NE);
        k_scan2<<<1, SCAN_B, 0, sC>>>(bsumsE, nb);
        k_scan3e<<<GRID1(NE), TB, 0, sC>>>(offE, bsumsE, curE, cnt, lattr, NE);
    }
    k_scat_gat<<<GRID1(E1), TB, 0, sC>>>(ent_ed, ent_lab, curE, E1);
    k_ce2<<<1, 64, 0, sC>>>(We1, ae1, We2, ae2);
    cudaEventRecord(eC, sC);

    // ---- main: value encoder, then GCN1 GEMM ----
    float* valfeat = nodesA + (size_t)NE*D;
    k_valenc_mma<<<(T + 63)/64, TB, SMEM_MMA>>>(triples, att, valf, Wp, valfeat, T);
    cudaStreamWaitEvent(0, eW, 0);
    k_gemm_pre<<<(N + 63)/64, TB, SMEM_MMA>>>(entf, valfeat, NE, w1hi, w1lo, hbuf,
                                              (const float*)0, D, N,
                                              (__nv_bfloat16*)0, 0,
                                              (const float*)0, (const float*)0, 0);

    // join B: aggregation needs CSR + dinv
    cudaStreamWaitEvent(0, eB, 0);
    k_gcn_csr<<<GRID1(N*32), TB>>>(hbuf, dinv, g1b, nodesB, off, deg, csrc, N);
    k_gcn_csr<<<GRID1(NE*32), TB>>>(nodesB, dinv, zerov, nodesA, off, deg, csrc, NE);

    // ---- GAT projections (GCN2 folded) -> bf16 hcat; als/ald in epilogue ----
    __nv_bfloat16* hcat = (__nv_bfloat16*)hbuf;
    cudaStreamWaitEvent(0, eWC, 0);
    k_gemm_pre<<<(NE + 63)/64, TB, SMEM_MMA>>>(nodesA, nodesA, NE, wc1hi, wc1lo,
                                               (float*)0, b1c, 256, NE,
                                               hcat, 0,   as1, ad1, 0);
    k_gemm_pre<<<(NE + 63)/64, TB, SMEM_MMA>>>(nodesA, nodesA, NE, wc2hi, wc2lo,
                                               (float*)0, b2c, 256, NE,
                                               hcat, 128, as2, ad2, 1);

    // join C: attention needs lattr/ce2/CSR(offE,cnt,gsl,gdst)
    cudaStreamWaitEvent(0, eC, 0);
    k_self_exp<<<GRID1(NE), TB>>>(lattr, NE);
    k_alpha_e <<<GRID1(E1), TB>>>(E1);
    k_gat_csr<<<GRID1(NE*32), TB>>>(hcat, entf, gb1, gb2, offE, cnt, out, NE);

    cudaEventDestroy(eF); cudaEventDestroy(eB); cudaEventDestroy(eW);
    cudaEventDestroy(eWC); cudaEventDestroy(eC);
    cudaStreamDestroy(sB); cudaStreamDestroy(sC);
    #undef GRID1
}

// round 17
// speedup vs baseline: 1.0623x; 1.0050x over previous
#include <cuda_runtime.h>
#include <cuda_bf16.h>
#include <cuda_fp16.h>
#include <math.h>
#include <stdint.h>

#define D 128
#define MAX_N   400000
#define MAX_E1  1000000
#define MAX_E2  500000
#define MAX_ENT 150000

// ---------------- device scratch ----------------
__device__ float    g_nodesA[(size_t)MAX_N * D];
__device__ float    g_nodesB[(size_t)MAX_N * D];
__device__ float    g_hbuf  [(size_t)MAX_N * D];   // GAT: fp16 hcat rows (256 half/row)
__device__ float    g_dinv  [MAX_N];
__device__ int      g_deg   [MAX_N];
__device__ int      g_off   [MAX_N];
__device__ int      g_cur   [MAX_N];
__device__ int      g_bsums [1024];
__device__ int      g_csrc  [MAX_E2];
__device__ int      g_offE  [MAX_ENT];
__device__ int      g_curE  [MAX_ENT];
__device__ int      g_bsumsE[1024];
__device__ float2   g_als2  [MAX_ENT];
__device__ float2   g_ald2  [MAX_ENT];
__device__ float2   g_eself2[MAX_ENT];
__device__ int      g_cnt   [MAX_ENT];
__device__ float    g_lattr [MAX_ENT];
__device__ int2     g_gsl   [MAX_E1];     // CSR payload: (src, label bits)
__device__ int      g_gdst  [MAX_E1];     // CSR slot -> dst
__device__ float4   g_gpe   [MAX_E1];     // packed: (src bits, e1, e2, pad)
__device__ float    g_ce2[2];
__device__ float    g_zerovec[D];
// pre-converted weights (bf16 hi/lo) + combined GAT weights/biases
__device__ __nv_bfloat16 g_w1hi[128*128],  g_w1lo[128*128];    // g1W
__device__ __nv_bfloat16 g_wc1hi[128*128], g_wc1lo[128*128];   // g2W@Wl1
__device__ __nv_bfloat16 g_wc2hi[128*128], g_wc2lo[128*128];   // g2W@Wl2
__device__ float    g_b1c[128], g_b2c[128];                    // g2b@Wl

// ---------------- small helpers ----------------
__device__ __forceinline__ float lrelu(float x){ return x > 0.f ? x : 0.2f * x; }
__device__ __forceinline__ uint32_t smem_u32(const void* p){
    uint32_t a; asm("{ .reg .u64 t; cvta.to.shared.u64 t, %1; cvt.u32.u64 %0, t; }" : "=r"(a) : "l"(p));
    return a;
}
__device__ __forceinline__ float4 f4axpy(float s, float4 a, float4 acc){
    acc.x += s*a.x; acc.y += s*a.y; acc.z += s*a.z; acc.w += s*a.w; return acc;
}
// 8 fp16 (uint4) -> 8 floats
__device__ __forceinline__ void h8tof(uint4 u, float (&f)[8]){
    const __half2* p = (const __half2*)&u;
    float2 a0 = __half22float2(p[0]);
    float2 a1 = __half22float2(p[1]);
    float2 a2 = __half22float2(p[2]);
    float2 a3 = __half22float2(p[3]);
    f[0]=a0.x; f[1]=a0.y; f[2]=a1.x; f[3]=a1.y;
    f[4]=a2.x; f[5]=a2.y; f[6]=a3.x; f[7]=a3.y;
}

// ---------------- mma.sync bf16x3 GEMM (64-row M tiles) ----------------
#define ASTR   136
#define AS_HI  0u
#define AS_LO  17408u
#define BS_HI2 34816u
#define BS_LO2 69632u
#define SMEM_MMA 104448

__device__ __forceinline__ void ldsm4(uint32_t (&r)[4], uint32_t addr){
    asm volatile("ldmatrix.sync.aligned.m8n8.x4.shared.b16 {%0,%1,%2,%3}, [%4];"
        : "=r"(r[0]), "=r"(r[1]), "=r"(r[2]), "=r"(r[3]) : "r"(addr));
}
__device__ __forceinline__ void ldsm4t(uint32_t &r0, uint32_t &r1, uint32_t &r2, uint32_t &r3, uint32_t addr){
    asm volatile("ldmatrix.sync.aligned.m8n8.x4.trans.shared.b16 {%0,%1,%2,%3}, [%4];"
        : "=r"(r0), "=r"(r1), "=r"(r2), "=r"(r3) : "r"(addr));
}
__device__ __forceinline__ void mma_bf16(float (&d)[4], const uint32_t (&a)[4], uint32_t b0, uint32_t b1){
    asm volatile("mma.sync.aligned.m16n8k16.row.col.f32.bf16.bf16.f32 "
        "{%0,%1,%2,%3}, {%4,%5,%6,%7}, {%8,%9}, {%0,%1,%2,%3};"
        : "+f"(d[0]), "+f"(d[1]), "+f"(d[2]), "+f"(d[3])
        : "r"(a[0]), "r"(a[1]), "r"(a[2]), "r"(a[3]), "r"(b0), "r"(b1));
}
__device__ __forceinline__ uint32_t frag_addr(uint32_t arr, int row0, int col0, int lane){
    int grp = lane >> 3, lr = lane & 7;
    int r = row0 + (grp & 1)*8 + lr;
    int c = col0 + (grp >> 1)*8;
    return arr + (uint32_t)(r*ASTR + c)*2u;
}
__device__ __forceinline__ void stage4(char* sm, uint32_t off_hi, uint32_t off_lo,
                                       int r, int c4, float4 v){
    __nv_bfloat16 h0 = __float2bfloat16_rn(v.x), h1 = __float2bfloat16_rn(v.y),
                  h2 = __float2bfloat16_rn(v.z), h3 = __float2bfloat16_rn(v.w);
    __nv_bfloat16 l0 = __float2bfloat16_rn(v.x - __bfloat162float(h0));
    __nv_bfloat16 l1 = __float2bfloat16_rn(v.y - __bfloat162float(h1));
    __nv_bfloat16 l2 = __float2bfloat16_rn(v.z - __bfloat162float(h2));
    __nv_bfloat16 l3 = __float2bfloat16_rn(v.w - __bfloat162float(h3));
    __nv_bfloat162 hp0, hp1, lp0, lp1;
    hp0.x = h0; hp0.y = h1; hp1.x = h2; hp1.y = h3;
    lp0.x = l0; lp0.y = l1; lp1.x = l2; lp1.y = l3;
    uint32_t byt = (uint32_t)(r*ASTR + c4*4)*2u;
    uint2 uh, ul;
    uh.x = *(uint32_t*)&hp0; uh.y = *(uint32_t*)&hp1;
    ul.x = *(uint32_t*)&lp0; ul.y = *(uint32_t*)&lp1;
    *(uint2*)(sm + off_hi + byt) = uh;
    *(uint2*)(sm + off_lo + byt) = ul;
}

__device__ __forceinline__ void mma_slab64(uint32_t smb, int wm, int n0, int lane,
                                           float (&acc)[8][4]){
#pragma unroll
    for (int kt = 0; kt < 8; ++kt){
        int k0 = kt*16;
        uint32_t ah[4], al[4], bh[8][2], bl[8][2];
        uint32_t adr = frag_addr(smb + AS_HI, wm*16, k0, lane);
        ldsm4(ah, adr);
        ldsm4(al, adr + (AS_LO - AS_HI));
#pragma unroll
        for (int nb = 0; nb < 4; ++nb){
            uint32_t badr = frag_addr(smb + BS_HI2, k0, n0 + nb*16, lane);
            ldsm4t(bh[2*nb][0], bh[2*nb][1], bh[2*nb+1][0], bh[2*nb+1][1], badr);
            ldsm4t(bl[2*nb][0], bl[2*nb][1], bl[2*nb+1][0], bl[2*nb+1][1],
                   badr + (BS_LO2 - BS_HI2));
        }
#pragma unroll
        for (int nt = 0; nt < 8; ++nt){
            mma_bf16(acc[nt], ah, bh[nt][0], bh[nt][1]);
            mma_bf16(acc[nt], ah, bl[nt][0], bl[nt][1]);
            mma_bf16(acc[nt], al, bh[nt][0], bh[nt][1]);
        }
    }
}

// C = A @ B (+bias); B pre-converted bf16 hi/lo.
// If ohf != 0: store fp16 into ohf (row stride 256 half, column offset ocol).
// Optional fused attention dots into g_als2/g_ald2 component comp.
__global__ void __launch_bounds__(256) k_gemm_pre(const float* __restrict__ Alow,
    const float* __restrict__ Ahigh, int split,
    const __nv_bfloat16* __restrict__ Bhi, const __nv_bfloat16* __restrict__ Blo,
    float* __restrict__ C, const float* __restrict__ bias, int ldc, int M,
    __half* __restrict__ ohf, int ocol,
    const float* __restrict__ asrc, const float* __restrict__ adst, int comp)
{
    extern __shared__ char sm[];
    const uint32_t smb = smem_u32(sm);
    const int tid = threadIdx.x, lane = tid & 31, wid = tid >> 5;
    const int wm = wid & 3, n0 = (wid >> 2)*64;
    const int m0 = blockIdx.x * 64;

#pragma unroll
    for (int i = 0; i < 8; ++i){
        int f = tid + i*256, r = f >> 5, c4 = f & 31;
        int row = m0 + r; if (row >= M) row = M - 1;
        const float* src = (row < split) ? (Alow + (size_t)row*D)
                                         : (Ahigh + (size_t)(row - split)*D);
        stage4(sm, AS_HI, AS_LO, r, c4, *(const float4*)(src + c4*4));
    }
#pragma unroll
    for (int i = 0; i < 8; ++i){
        int f = tid + i*256;
        int r = f >> 4, c = f & 15;
        uint32_t dst = (uint32_t)(r*(ASTR*2) + c*16);
        *(uint4*)(sm + BS_HI2 + dst) = ((const uint4*)Bhi)[f];
        *(uint4*)(sm + BS_LO2 + dst) = ((const uint4*)Blo)[f];
    }
    __syncthreads();

    float acc[8][4];
#pragma unroll
    for (int nt = 0; nt < 8; ++nt)
#pragma unroll
        for (int j = 0; j < 4; ++j) acc[nt][j] = 0.f;

    mma_slab64(smb, wm, n0, lane, acc);

#pragma unroll
    for (int nt = 0; nt < 8; ++nt){
        int c = n0 + nt*8 + (lane & 3)*2;
        float b0 = bias ? bias[c] : 0.f, b1v = bias ? bias[c+1] : 0.f;
        acc[nt][0] += b0; acc[nt][1] += b1v;
        acc[nt][2] += b0; acc[nt][3] += b1v;
        int r = m0 + wm*16 + (lane >> 2);
        if (ohf){
            __half2 v0 = __floats2half2_rn(acc[nt][0], acc[nt][1]);
            __half2 v1 = __floats2half2_rn(acc[nt][2], acc[nt][3]);
            if (r < M)
                *(uint32_t*)(ohf + (size_t)r*256 + ocol + c) = *(uint32_t*)&v0;
            if (r + 8 < M)
                *(uint32_t*)(ohf + (size_t)(r+8)*256 + ocol + c) = *(uint32_t*)&v1;
        } else {
            if (r < M)
                *(float2*)(C + (size_t)r*ldc + c) = make_float2(acc[nt][0], acc[nt][1]);
            if (r + 8 < M)
                *(float2*)(C + (size_t)(r+8)*ldc + c) = make_float2(acc[nt][2], acc[nt][3]);
        }
    }

    if (asrc){
        float* red = (float*)sm;   // [0..63]=als rows, [64..127]=ald rows
        __syncthreads();
        if (tid < 128) red[tid] = 0.f;
        __syncthreads();
        float pa = 0.f, pa8 = 0.f, pd = 0.f, pd8 = 0.f;
#pragma unroll
        for (int nt = 0; nt < 8; ++nt){
            int c = n0 + nt*8 + (lane & 3)*2;
            float s0 = asrc[c], s1 = asrc[c+1], t0 = adst[c], t1 = adst[c+1];
            pa  += acc[nt][0]*s0 + acc[nt][1]*s1;
            pa8 += acc[nt][2]*s0 + acc[nt][3]*s1;
            pd  += acc[nt][0]*t0 + acc[nt][1]*t1;
            pd8 += acc[nt][2]*t0 + acc[nt][3]*t1;
        }
#pragma unroll
        for (int o = 1; o <= 2; o <<= 1){
            pa  += __shfl_xor_sync(0xffffffffu, pa,  o);
            pa8 += __shfl_xor_sync(0xffffffffu, pa8, o);
            pd  += __shfl_xor_sync(0xffffffffu, pd,  o);
            pd8 += __shfl_xor_sync(0xffffffffu, pd8, o);
        }
        if ((lane & 3) == 0){
            int lr = wm*16 + (lane >> 2);
            atomicAdd(red + lr,          pa);
            atomicAdd(red + lr + 8,      pa8);
            atomicAdd(red + 64 + lr,     pd);
            atomicAdd(red + 64 + lr + 8, pd8);
        }
        __syncthreads();
        if (tid < 64 && m0 + tid < M){
            ((float*)g_als2)[(size_t)(m0 + tid)*2 + comp] = red[tid];
            ((float*)g_ald2)[(size_t)(m0 + tid)*2 + comp] = red[64 + tid];
        }
    }
}

// C[t,:] = concat(att[a_t], val[v_t]) @ W (K=256), on-the-fly B convert
__global__ void __launch_bounds__(256) k_valenc_mma(const int* __restrict__ triples,
    const float* __restrict__ att, const float* __restrict__ val,
    const float* __restrict__ W, float* __restrict__ C, int T)
{
    extern __shared__ char sm[];
    __shared__ int idxA[64], idxV[64];
    const uint32_t smb = smem_u32(sm);
    const int tid = threadIdx.x, lane = tid & 31, wid = tid >> 5;
    const int wm = wid & 3, n0 = (wid >> 2)*64;
    const int m0 = blockIdx.x * 64;
    if (tid < 64){
        int t = m0 + tid; if (t >= T) t = T - 1;
        idxV[tid] = triples[3*t + 1];
        idxA[tid] = triples[3*t + 2];
    }
    __syncthreads();

    float acc[8][4];
#pragma unroll
    for (int nt = 0; nt < 8; ++nt)
#pragma unroll
        for (int j = 0; j < 4; ++j) acc[nt][j] = 0.f;

    for (int ph = 0; ph < 2; ++ph){
        if (ph) __syncthreads();
#pragma unroll
        for (int i = 0; i < 8; ++i){
            int f = tid + i*256, r = f >> 5, c4 = f & 31;
            const float* src = ph ? (val + (size_t)idxV[r]*D) : (att + (size_t)idxA[r]*D);
            stage4(sm, AS_HI, AS_LO, r, c4, *(const float4*)(src + c4*4));
        }
        const float* Wph = W + (size_t)ph*128*D;
#pragma unroll
        for (int i = 0; i < 16; ++i){
            int f = tid + i*256, r = f >> 5, c4 = f & 31;
            stage4(sm, BS_HI2, BS_LO2, r, c4, *(const float4*)(Wph + (size_t)r*D + c4*4));
        }
        __syncthreads();
        mma_slab64(smb, wm, n0, lane, acc);
    }

#pragma unroll
    for (int nt = 0; nt < 8; ++nt){
        int r = m0 + wm*16 + (lane >> 2);
        int c = n0 + nt*8 + (lane & 3)*2;
        if (r < T)
            *(float2*)(C + (size_t)r*D + c) = make_float2(acc[nt][0], acc[nt][1]);
        if (r + 8 < T)
            *(float2*)(C + (size_t)(r+8)*D + c) = make_float2(acc[nt][2], acc[nt][3]);
    }
}

// ---------------- weight prep ----------------
__global__ void k_conv(const float* __restrict__ W, __nv_bfloat16* __restrict__ hi,
                       __nv_bfloat16* __restrict__ lo, int n4){
    int i = blockIdx.x*blockDim.x + threadIdx.x;
    if (i >= n4) return;
    float4 v = ((const float4*)W)[i];
    __nv_bfloat16 h0 = __float2bfloat16_rn(v.x), h1 = __float2bfloat16_rn(v.y),
                  h2 = __float2bfloat16_rn(v.z), h3 = __float2bfloat16_rn(v.w);
    hi[4*i]   = h0; hi[4*i+1] = h1; hi[4*i+2] = h2; hi[4*i+3] = h3;
    lo[4*i]   = __float2bfloat16_rn(v.x - __bfloat162float(h0));
    lo[4*i+1] = __float2bfloat16_rn(v.y - __bfloat162float(h1));
    lo[4*i+2] = __float2bfloat16_rn(v.z - __bfloat162float(h2));
    lo[4*i+3] = __float2bfloat16_rn(v.w - __bfloat162float(h3));
}
__global__ void __launch_bounds__(128) k_wcomb(const float* __restrict__ A,
    const float* __restrict__ B, const float* __restrict__ bvec,
    __nv_bfloat16* __restrict__ chi, __nv_bfloat16* __restrict__ clo,
    float* __restrict__ bc)
{
    __shared__ float Ar[128];
    int r = blockIdx.x, c = threadIdx.x;
    const float* row = (r < 128) ? (A + r*128) : bvec;
    Ar[c] = row[c];
    __syncthreads();
    float acc = 0.f;
#pragma unroll 8
    for (int k = 0; k < 128; ++k) acc += Ar[k]*B[k*128 + c];
    if (r < 128){
        __nv_bfloat16 h = __float2bfloat16_rn(acc);
        chi[r*128 + c] = h;
        clo[r*128 + c] = __float2bfloat16_rn(acc - __bfloat162float(h));
    } else {
        bc[c] = acc;
    }
}

// ---------------- scan ----------------
#define SCAN_B 1024
__global__ void k_scan1(const int* __restrict__ in, int* __restrict__ out,
                        int* __restrict__ bsums, int n){
    __shared__ int s[SCAN_B];
    int t = threadIdx.x, idx = blockIdx.x*SCAN_B + t;
    int v = (idx < n) ? in[idx] : 0;
    s[t] = v; __syncthreads();
    for (int o = 1; o < SCAN_B; o <<= 1){
        int x = (t >= o) ? s[t-o] : 0; __syncthreads();
        s[t] += x; __syncthreads();
    }
    if (idx < n) out[idx] = s[t] - v;
    if (t == SCAN_B-1) bsums[blockIdx.x] = s[t];
}
__global__ void k_scan2(int* __restrict__ bsums, int nb){
    __shared__ int s[SCAN_B];
    int t = threadIdx.x;
    int v = (t < nb) ? bsums[t] : 0;
    s[t] = v; __syncthreads();
    for (int o = 1; o < SCAN_B; o <<= 1){
        int x = (t >= o) ? s[t-o] : 0; __syncthreads();
        s[t] += x; __syncthreads();
    }
    if (t < nb) bsums[t] = s[t] - v;
}
__global__ void k_scan3v(int* __restrict__ off, const int* __restrict__ bsums,
                         int* __restrict__ cur, const int* __restrict__ deg,
                         float* __restrict__ dinv, int n){
    int idx = blockIdx.x*blockDim.x + threadIdx.x;
    if (idx < n){
        int o = off[idx] + bsums[idx >> 10];
        off[idx] = o; cur[idx] = o;
        dinv[idx] = rsqrtf((float)(deg[idx] + 1));
    }
}
__global__ void k_scan3e(int* __restrict__ off, const int* __restrict__ bsums,
                         int* __restrict__ cur, const int* __restrict__ cnt,
                         float* __restrict__ ls, int n){
    int idx = blockIdx.x*blockDim.x + threadIdx.x;
    if (idx < n){
        int o = off[idx] + bsums[idx >> 10];
        off[idx] = o; cur[idx] = o;
        ls[idx] = ls[idx] / fmaxf((float)cnt[idx], 1.f);
    }
}

// ---------------- elementwise / build kernels ----------------
__global__ void k_seti(int* p, int v, int n){
    int i = blockIdx.x*blockDim.x + threadIdx.x; if (i < n) p[i] = v;
}
__global__ void k_init_gat(int* __restrict__ cnt, float* __restrict__ ls, int n){
    int i = blockIdx.x*blockDim.x + threadIdx.x;
    if (i < n){ cnt[i] = 0; ls[i] = 0.f; }
}
__global__ void k_deg_acc(const int2* __restrict__ ed, int* deg, int E){
    int i = blockIdx.x*blockDim.x + threadIdx.x;
    if (i < E) atomicAdd(deg + ed[i].y, 1);
}
__global__ void k_scat_val(const int2* __restrict__ ed, int* cur, int* csrc, int E){
    int i = blockIdx.x*blockDim.x + threadIdx.x;
    if (i >= E) return;
    int2 sd = ed[i];
    int pos = atomicAdd(cur + sd.y, 1);
    csrc[pos] = sd.x;
}
__global__ void k_scat_gat(const int2* __restrict__ ed, const float* __restrict__ lab,
                           int* cur, int E){
    int i = blockIdx.x*blockDim.x + threadIdx.x;
    if (i >= E) return;
    int2 sd = ed[i];
    int pos = atomicAdd(cur + sd.y, 1);
    g_gsl[pos] = make_int2(sd.x, __float_as_int(lab[i]));
    g_gdst[pos] = sd.y;
}
// warp per dst; 2-way unrolled edge loop (fp32 features)
__global__ void k_gcn_csr(const float* __restrict__ h, const float* __restrict__ dinv,
                          const float* __restrict__ b, float* __restrict__ out,
                          const int* __restrict__ off, const int* __restrict__ deg,
                          const int* __restrict__ csrc, int M)
{
    int g = blockIdx.x*blockDim.x + threadIdx.x;
    int lane = g & 31, d = g >> 5;
    if (d >= M) return;
    float did = dinv[d];
    float4 hv = ((const float4*)(h + (size_t)d*D))[lane];
    float4 acc = *(const float4*)(b + lane*4);
    acc = f4axpy(did*did, hv, acc);
    int e0 = off[d], n = deg[d];
    int e = e0, eend = e0 + n;
    for (; e + 1 < eend; e += 2){
        int s0 = csrc[e], s1 = csrc[e+1];
        float dv0 = dinv[s0], dv1 = dinv[s1];
        float4 x0 = ((const float4*)(h + (size_t)s0*D))[lane];
        float4 x1 = ((const float4*)(h + (size_t)s1*D))[lane];
        acc = f4axpy(dv0*did, x0, acc);
        acc = f4axpy(dv1*did, x1, acc);
    }
    if (e < eend){
        int s = csrc[e];
        float4 xv = ((const float4*)(h + (size_t)s*D))[lane];
        acc = f4axpy(dinv[s]*did, xv, acc);
    }
    ((float4*)(out + (size_t)d*D))[lane] = acc;
}
__global__ void k_cnt(const int2* __restrict__ ed, const float* __restrict__ lab,
                      int* cnt, float* ls, int E){
    int i = blockIdx.x*blockDim.x + threadIdx.x;
    if (i < E){ int d = ed[i].y; atomicAdd(cnt + d, 1); atomicAdd(ls + d, lab[i]); }
}
__global__ void k_ce2(const float* __restrict__ We1, const float* __restrict__ ae1,
                      const float* __restrict__ We2, const float* __restrict__ ae2){
    int t = threadIdx.x;
    int lane = t & 31, w = t >> 5;
    const float* We = w ? We2 : We1;
    const float* ae = w ? ae2 : ae1;
    float s = 0.f;
    for (int i = lane; i < D; i += 32) s += We[i]*ae[i];
#pragma unroll
    for (int o = 16; o; o >>= 1) s += __shfl_xor_sync(0xffffffffu, s, o);
    if (lane == 0) g_ce2[w] = s;
}
__global__ void k_self_exp(const float* __restrict__ lattr, int n){
    int i = blockIdx.x*blockDim.x + threadIdx.x;
    if (i < n){
        float2 als = g_als2[i], ald = g_ald2[i];
        float la = lattr[i];
        g_eself2[i] = make_float2(__expf(lrelu(als.x + ald.x + la*g_ce2[0])),
                                  __expf(lrelu(als.y + ald.y + la*g_ce2[1])));
    }
}
__global__ void k_alpha_e(int E){
    int i = blockIdx.x*blockDim.x + threadIdx.x;
    if (i >= E) return;
    int2 sl = g_gsl[i];
    int d = g_gdst[i];
    float lab = __int_as_float(sl.y);
    float2 als = g_als2[sl.x];
    float2 ald = g_ald2[d];
    float e1 = __expf(lrelu(als.x + ald.x + lab*g_ce2[0]));
    float e2 = __expf(lrelu(als.y + ald.y + lab*g_ce2[1]));
    g_gpe[i] = make_float4(__int_as_float(sl.x), e1, e2, 0.f);
}
// warp per dst over fp16 hcat: lane<16 -> 8 h1-cols, lane>=16 -> 8 h2-cols.
// One 16B load per lane per edge. Layers combined via shfl at the end.
__global__ void k_gat_csr(const __half* __restrict__ hcat,
                          const float* __restrict__ ent,
                          const float* __restrict__ b1, const float* __restrict__ b2,
                          const int* __restrict__ off, const int* __restrict__ cnt,
                          float* __restrict__ out, int M)
{
    int g = blockIdx.x*blockDim.x + threadIdx.x;
    int lane = g & 31, d = g >> 5;
    if (d >= M) return;
    float2 es = g_eself2[d];
    float wself = (lane < 16) ? es.x : es.y;
    const uint4* hrow = (const uint4*)(hcat + (size_t)d*256);
    float hv[8]; h8tof(hrow[lane], hv);
    float acc[8];
#pragma unroll
    for (int j = 0; j < 8; ++j) acc[j] = wself*hv[j];
    float z1 = es.x, z2 = es.y;
    int e0 = off[d], n = cnt[d];
    int e = e0, eend = e0 + n;
    for (; e + 1 < eend; e += 2){
        float4 p0 = g_gpe[e], p1 = g_gpe[e+1];
        const uint4* r0 = (const uint4*)(hcat + (size_t)__float_as_int(p0.x)*256);
        const uint4* r1 = (const uint4*)(hcat + (size_t)__float_as_int(p1.x)*256);
        uint4 u0 = r0[lane], u1 = r1[lane];
        float w0 = (lane < 16) ? p0.y : p0.z;
        float w1 = (lane < 16) ? p1.y : p1.z;
        float x0[8], x1[8];
        h8tof(u0, x0); h8tof(u1, x1);
#pragma unroll
        for (int j = 0; j < 8; ++j) acc[j] += w0*x0[j] + w1*x1[j];
        z1 += p0.y + p1.y; z2 += p0.z + p1.z;
    }
    if (e < eend){
        float4 p = g_gpe[e];
        const uint4* r = (const uint4*)(hcat + (size_t)__float_as_int(p.x)*256);
        uint4 u = r[lane];
        float w = (lane < 16) ? p.y : p.z;
        float x[8]; h8tof(u, x);
#pragma unroll
        for (int j = 0; j < 8; ++j) acc[j] += w*x[j];
        z1 += p.y; z2 += p.z;
    }
    float i1 = 1.f/(z1 + 1e-16f), i2 = 1.f/(z2 + 1e-16f);
    float wn = (lane < 16) ? i1 : i2;
#pragma unroll
    for (int j = 0; j < 8; ++j) acc[j] *= wn;
    float oth[8];
#pragma unroll
    for (int j = 0; j < 8; ++j)
        oth[j] = __shfl_down_sync(0xffffffffu, acc[j], 16);
    if (lane < 16){
        int c0 = lane*8;
        const float* ep = ent + (size_t)d*D + c0;
        float4 e1v = *(const float4*)(ep);
        float4 e2v = *(const float4*)(ep + 4);
        float4 q1 = *(const float4*)(b1 + c0);
        float4 q2 = *(const float4*)(b1 + c0 + 4);
        float4 r1v = *(const float4*)(b2 + c0);
        float4 r2v = *(const float4*)(b2 + c0 + 4);
        float* op = out + (size_t)d*D + c0;
        *(float4*)(op) = make_float4(
            e1v.x + q1.x + r1v.x + acc[0] + oth[0],
            e1v.y + q1.y + r1v.y + acc[1] + oth[1],
            e1v.z + q1.z + r1v.z + acc[2] + oth[2],
            e1v.w + q1.w + r1v.w + acc[3] + oth[3]);
        *(float4*)(op + 4) = make_float4(
            e2v.x + q2.x + r2v.x + acc[4] + oth[4],
            e2v.y + q2.y + r2v.y + acc[5] + oth[5],
            e2v.z + q2.z + r2v.z + acc[6] + oth[6],
            e2v.w + q2.w + r2v.w + acc[7] + oth[7]);
    }
}

// ---------------- launcher ----------------
extern "C" void kernel_launch(void* const* d_in, const int* in_sizes, int n_in,
                              void* d_out, int out_size)
{
    const int*   triples  = (const int*)  d_in[0];
    const int2*  ent_ed   = (const int2*) d_in[1];
    const float* ent_lab  = (const float*)d_in[2];
    const int2*  val_ed   = (const int2*) d_in[3];
    const float* att      = (const float*)d_in[5];
    const float* valf     = (const float*)d_in[6];
    const float* entf     = (const float*)d_in[7];
    const float* Wp       = (const float*)d_in[8];
    const float* g1W      = (const float*)d_in[9];
    const float* g1b      = (const float*)d_in[10];
    const float* g2W      = (const float*)d_in[11];
    const float* g2b      = (const float*)d_in[12];
    const float* Wl1      = (const float*)d_in[13];
    const float* as1      = (const float*)d_in[14];
    const float* ad1      = (const float*)d_in[15];
    const float* We1      = (const float*)d_in[16];
    const float* ae1      = (const float*)d_in[17];
    const float* gb1      = (const float*)d_in[18];
    const float* Wl2      = (const float*)d_in[19];
    const float* as2      = (const float*)d_in[20];
    const float* ad2      = (const float*)d_in[21];
    const float* We2      = (const float*)d_in[22];
    const float* ae2      = (const float*)d_in[23];
    const float* gb2      = (const float*)d_in[24];

    const int T   = in_sizes[0] / 3;
    const int E1  = in_sizes[1] / 2;
    const int E2  = in_sizes[3] / 2;
    const int NE  = in_sizes[7] / D;
    const int N   = NE + T;
    float* out = (float*)d_out;

    float *nodesA, *nodesB, *hbuf, *dinv, *lattr, *zerov, *b1c, *b2c;
    int *deg, *cnt, *off, *cur, *bsums, *csrc, *offE, *curE, *bsumsE;
    __nv_bfloat16 *w1hi, *w1lo, *wc1hi, *wc1lo, *wc2hi, *wc2lo;
    cudaGetSymbolAddress((void**)&nodesA, g_nodesA);
    cudaGetSymbolAddress((void**)&nodesB, g_nodesB);
    cudaGetSymbolAddress((void**)&hbuf,   g_hbuf);
    cudaGetSymbolAddress((void**)&dinv,   g_dinv);
    cudaGetSymbolAddress((void**)&deg,    g_deg);
    cudaGetSymbolAddress((void**)&cnt,    g_cnt);
    cudaGetSymbolAddress((void**)&lattr,  g_lattr);
    cudaGetSymbolAddress((void**)&zerov,  g_zerovec);
    cudaGetSymbolAddress((void**)&off,    g_off);
    cudaGetSymbolAddress((void**)&cur,    g_cur);
    cudaGetSymbolAddress((void**)&bsums,  g_bsums);
    cudaGetSymbolAddress((void**)&csrc,   g_csrc);
    cudaGetSymbolAddress((void**)&offE,   g_offE);
    cudaGetSymbolAddress((void**)&curE,   g_curE);
    cudaGetSymbolAddress((void**)&bsumsE, g_bsumsE);
    cudaGetSymbolAddress((void**)&w1hi,   g_w1hi);
    cudaGetSymbolAddress((void**)&w1lo,   g_w1lo);
    cudaGetSymbolAddress((void**)&wc1hi,  g_wc1hi);
    cudaGetSymbolAddress((void**)&wc1lo,  g_wc1lo);
    cudaGetSymbolAddress((void**)&wc2hi,  g_wc2hi);
    cudaGetSymbolAddress((void**)&wc2lo,  g_wc2lo);
    cudaGetSymbolAddress((void**)&b1c,    g_b1c);
    cudaGetSymbolAddress((void**)&b2c,    g_b2c);

    cudaFuncSetAttribute(k_gemm_pre,   cudaFuncAttributeMaxDynamicSharedMemorySize, SMEM_MMA);
    cudaFuncSetAttribute(k_valenc_mma, cudaFuncAttributeMaxDynamicSharedMemorySize, SMEM_MMA);

    const int TB = 256;
    #define GRID1(n) (((n) + TB - 1) / TB)

    cudaStream_t sB, sC;
    cudaStreamCreateWithFlags(&sB, cudaStreamNonBlocking);
    cudaStreamCreateWithFlags(&sC, cudaStreamNonBlocking);
    cudaEvent_t eF, eB, eW, eWC, eC;
    cudaEventCreateWithFlags(&eF,  cudaEventDisableTiming);
    cudaEventCreateWithFlags(&eB,  cudaEventDisableTiming);
    cudaEventCreateWithFlags(&eW,  cudaEventDisableTiming);
    cudaEventCreateWithFlags(&eWC, cudaEventDisableTiming);
    cudaEventCreateWithFlags(&eC,  cudaEventDisableTiming);
    cudaEventRecord(eF, 0);
    cudaStreamWaitEvent(sB, eF, 0);
    cudaStreamWaitEvent(sC, eF, 0);

    // ---- branch B: val-edge CSR + dinv ----
    k_seti   <<<GRID1(N), TB, 0, sB>>>(deg, 0, N);
    k_deg_acc<<<GRID1(E2), TB, 0, sB>>>(val_ed, deg, E2);
    {
        int nb = (N + SCAN_B - 1)/SCAN_B;
        k_scan1<<<nb, SCAN_B, 0, sB>>>(deg, off, bsums, N);
        k_scan2<<<1, SCAN_B, 0, sB>>>(bsums, nb);
        k_scan3v<<<GRID1(N), TB, 0, sB>>>(off, bsums, cur, deg, dinv, N);
    }
    k_scat_val<<<GRID1(E2), TB, 0, sB>>>(val_ed, cur, csrc, E2);
    cudaEventRecord(eB, sB);

    // ---- branch C: weight prep + full GAT CSR (incl. payload) + lattr + ce2 ----
    k_conv <<<(128*128/4 + TB - 1)/TB, TB, 0, sC>>>(g1W, w1hi, w1lo, 128*128/4);
    cudaEventRecord(eW, sC);
    k_wcomb<<<129, 128, 0, sC>>>(g2W, Wl1, g2b, wc1hi, wc1lo, b1c);
    k_wcomb<<<129, 128, 0, sC>>>(g2W, Wl2, g2b, wc2hi, wc2lo, b2c);
    cudaEventRecord(eWC, sC);
    k_init_gat<<<GRID1(NE), TB, 0, sC>>>(cnt, lattr, NE);
    k_cnt     <<<GRID1(E1), TB, 0, sC>>>(ent_ed, ent_lab, cnt, lattr, E1);
    {
        int nb = (NE + SCAN_B - 1)/SCAN_B;
        k_scan1<<<nb, SCAN_B, 0, sC>>>(cnt, offE, bsumsE, NE);
        k_scan2<<<1, SCAN_B, 0, sC>>>(bsumsE, nb);
        k_scan3e<<<GRID1(NE), TB, 0, sC>>>(offE, bsumsE, curE, cnt, lattr, NE);
    }
    k_scat_gat<<<GRID1(E1), TB, 0, sC>>>(ent_ed, ent_lab, curE, E1);
    k_ce2<<<1, 64, 0, sC>>>(We1, ae1, We2, ae2);
    cudaEventRecord(eC, sC);

    // ---- main: value encoder, then GCN1 GEMM ----
    float* valfeat = nodesA + (size_t)NE*D;
    k_valenc_mma<<<(T + 63)/64, TB, SMEM_MMA>>>(triples, att, valf, Wp, valfeat, T);
    cudaStreamWaitEvent(0, eW, 0);
    k_gemm_pre<<<(N + 63)/64, TB, SMEM_MMA>>>(entf, valfeat, NE, w1hi, w1lo, hbuf,
                                              (const float*)0, D, N,
                                              (__half*)0, 0,
                                              (const float*)0, (const float*)0, 0);

    // join B: aggregation needs CSR + dinv
    cudaStreamWaitEvent(0, eB, 0);
    k_gcn_csr<<<GRID1(N*32), TB>>>(hbuf, dinv, g1b, nodesB, off, deg, csrc, N);
    k_gcn_csr<<<GRID1(NE*32), TB>>>(nodesB, dinv, zerov, nodesA, off, deg, csrc, NE);

    // ---- GAT projections (GCN2 folded) -> fp16 hcat; als/ald in epilogue ----
    __half* hcat = (__half*)hbuf;
    cudaStreamWaitEvent(0, eWC, 0);
    k_gemm_pre<<<(NE + 63)/64, TB, SMEM_MMA>>>(nodesA, nodesA, NE, wc1hi, wc1lo,
                                               (float*)0, b1c, 256, NE,
                                               hcat, 0,   as1, ad1, 0);
    k_gemm_pre<<<(NE + 63)/64, TB, SMEM_MMA>>>(nodesA, nodesA, NE, wc2hi, wc2lo,
                                               (float*)0, b2c, 256, NE,
                                               hcat, 128, as2, ad2, 1);

    // join C: attention needs lattr/ce2/CSR(offE,cnt,gsl,gdst)
    cudaStreamWaitEvent(0, eC, 0);
    k_self_exp<<<GRID1(NE), TB>>>(lattr, NE);
    k_alpha_e <<<GRID1(E1), TB>>>(E1);
    k_gat_csr<<<GRID1(NE*32), TB>>>(hcat, entf, gb1, gb2, offE, cnt, out, NE);

    cudaEventDestroy(eF); cudaEventDestroy(eB); cudaEventDestroy(eW);
    cudaEventDestroy(eWC); cudaEventDestroy(eC);
    cudaStreamDestroy(sB); cudaStreamDestroy(sC);
    #undef GRID1
}